// round 1
// baseline (speedup 1.0000x reference)
#include <cuda_runtime.h>
#include <cuda_bf16.h>
#include <cstddef>

// Problem constants
#define NB   16
#define CIN  2048
#define MID  512          // heads*dv = 4*128
#define HW   1024         // 32*32
#define DQK  128
#define NHEAD 4
#define ATT_SCALE 0.08838834764831845f   // 1/sqrt(128)
#define BN_EPS 1e-5f

// Tile config
#define BM 128
#define BN_ 128
#define BK 16
#define LDS_ (BM + 4)     // padded smem row (multiple of 4 for float4)

// Scratch (device globals — allocation-free kernel_launch)
__device__ float g_out1  [(size_t)NB * MID * HW];          //  33.5 MB
__device__ float g_qk    [(size_t)NB * 1024 * HW];         //  67 MB   (q' then k')
__device__ float g_v     [(size_t)NB * MID * HW];          //  33.5 MB
__device__ float g_logits[(size_t)NB * NHEAD * HW * HW];   // 268 MB
__device__ float g_attn  [(size_t)NB * MID * HW];          //  33.5 MB

// ---------------------------------------------------------------------------
// Tile loaders. 256 threads per block.
// load_tileT: src is [rows, K] row-major (row stride ld); loads a [128 x 16]
//             tile at src (already offset to tile origin) transposed into
//             s[k][row].
// load_tileD: src is [K, cols] row-major (row stride ld); loads a [16 x 128]
//             tile directly into s[k][col].
// ---------------------------------------------------------------------------
__device__ __forceinline__ void load_tileT(float* s, const float* __restrict__ src,
                                           int ld, int tid) {
#pragma unroll
    for (int r = 0; r < 2; r++) {
        int f   = tid + r * 256;       // 0..511 float4s
        int row = f >> 2;              // 0..127
        int kq  = (f & 3) * 4;         // 0,4,8,12
        float4 v = *(const float4*)(src + (size_t)row * ld + kq);
        s[(kq + 0) * LDS_ + row] = v.x;
        s[(kq + 1) * LDS_ + row] = v.y;
        s[(kq + 2) * LDS_ + row] = v.z;
        s[(kq + 3) * LDS_ + row] = v.w;
    }
}

__device__ __forceinline__ void load_tileD(float* s, const float* __restrict__ src,
                                           int ld, int tid) {
#pragma unroll
    for (int r = 0; r < 2; r++) {
        int f   = tid + r * 256;
        int k   = f >> 5;              // 0..15
        int col = (f & 31) * 4;        // 0..124
        *(float4*)(s + k * LDS_ + col) = *(const float4*)(src + (size_t)k * ld + col);
    }
}

__device__ __forceinline__ void mma16(const float* As, const float* Bs,
                                      float acc[8][8], int ty8, int tx8) {
#pragma unroll
    for (int k = 0; k < BK; k++) {
        float4 a0 = *(const float4*)(As + k * LDS_ + ty8);
        float4 a1 = *(const float4*)(As + k * LDS_ + ty8 + 4);
        float4 b0 = *(const float4*)(Bs + k * LDS_ + tx8);
        float4 b1 = *(const float4*)(Bs + k * LDS_ + tx8 + 4);
        float a[8] = {a0.x, a0.y, a0.z, a0.w, a1.x, a1.y, a1.z, a1.w};
        float b[8] = {b0.x, b0.y, b0.z, b0.w, b1.x, b1.y, b1.z, b1.w};
#pragma unroll
        for (int i = 0; i < 8; i++)
#pragma unroll
            for (int j = 0; j < 8; j++)
                acc[i][j] = fmaf(a[i], b[j], acc[i][j]);
    }
}

// ---------------------------------------------------------------------------
// GEMM1: out1 = relu(BN(conv1_w @ x_n))      W[512,2048] @ A[2048,1024]
// ---------------------------------------------------------------------------
__global__ __launch_bounds__(256) void k_gemm1(
    const float* __restrict__ x, const float* __restrict__ w,
    const float* __restrict__ gamma, const float* __restrict__ beta,
    const float* __restrict__ mean, const float* __restrict__ var) {
    __shared__ float As[BK * LDS_];
    __shared__ float Bs[BK * LDS_];
    int n = blockIdx.z, m0 = blockIdx.y * BM, n0 = blockIdx.x * BN_;
    int tid = threadIdx.x;
    int ty8 = (tid >> 4) * 8, tx8 = (tid & 15) * 8;
    const float* a  = x + (size_t)n * CIN * HW + n0;
    const float* wp = w + (size_t)m0 * CIN;
    float acc[8][8] = {};
    for (int k0 = 0; k0 < CIN; k0 += BK) {
        load_tileT(As, wp + k0, CIN, tid);
        load_tileD(Bs, a + (size_t)k0 * HW, HW, tid);
        __syncthreads();
        mma16(As, Bs, acc, ty8, tx8);
        __syncthreads();
    }
    float* outp = g_out1 + (size_t)n * MID * HW + n0 + tx8;
#pragma unroll
    for (int i = 0; i < 8; i++) {
        int o = m0 + ty8 + i;
        float inv  = gamma[o] * rsqrtf(var[o] + BN_EPS);
        float bias = beta[o] - mean[o] * inv;
        float r[8];
#pragma unroll
        for (int j = 0; j < 8; j++) r[j] = fmaxf(acc[i][j] * inv + bias, 0.f);
        *(float4*)(outp + (size_t)o * HW)     = make_float4(r[0], r[1], r[2], r[3]);
        *(float4*)(outp + (size_t)o * HW + 4) = make_float4(r[4], r[5], r[6], r[7]);
    }
}

// ---------------------------------------------------------------------------
// GEMM2: [qk ; v] = [qk_w ; v_w] @ out1_n    (M=1536, K=512)
// epilogue: q channels (o<512)      -> *SCALE           -> g_qk
//           k channels (512..1023)  -> + emb[pos, d]    -> g_qk
//           v channels (1024..1535) -> plain            -> g_v
// ---------------------------------------------------------------------------
__global__ __launch_bounds__(256) void k_gemm2(
    const float* __restrict__ qk_w, const float* __restrict__ v_w,
    const float* __restrict__ pos_h, const float* __restrict__ pos_w) {
    __shared__ float As[BK * LDS_];
    __shared__ float Bs[BK * LDS_];
    int n = blockIdx.z, m0 = blockIdx.y * BM, n0 = blockIdx.x * BN_;
    int tid = threadIdx.x;
    int ty8 = (tid >> 4) * 8, tx8 = (tid & 15) * 8;
    const float* wp = (m0 < 1024) ? qk_w + (size_t)m0 * MID
                                  : v_w + (size_t)(m0 - 1024) * MID;
    const float* a = g_out1 + (size_t)n * MID * HW + n0;
    float acc[8][8] = {};
    for (int k0 = 0; k0 < MID; k0 += BK) {
        load_tileT(As, wp + k0, MID, tid);
        load_tileD(Bs, a + (size_t)k0 * HW, HW, tid);
        __syncthreads();
        mma16(As, Bs, acc, ty8, tx8);
        __syncthreads();
    }
#pragma unroll
    for (int i = 0; i < 8; i++) {
        int o = m0 + ty8 + i;
        float r[8];
        if (o < 512) {                      // q' = q * scale
#pragma unroll
            for (int j = 0; j < 8; j++) r[j] = acc[i][j] * ATT_SCALE;
            float* p = g_qk + (size_t)n * 1024 * HW + (size_t)o * HW + n0 + tx8;
            *(float4*)p       = make_float4(r[0], r[1], r[2], r[3]);
            *(float4*)(p + 4) = make_float4(r[4], r[5], r[6], r[7]);
        } else if (o < 1024) {              // k' = k + emb[y, d]
            int d = (o - 512) & 127;
#pragma unroll
            for (int j = 0; j < 8; j++) {
                int y = n0 + tx8 + j;
                float emb = pos_h[(y >> 5) * DQK + d] + pos_w[(y & 31) * DQK + d];
                r[j] = acc[i][j] + emb;
            }
            float* p = g_qk + (size_t)n * 1024 * HW + (size_t)o * HW + n0 + tx8;
            *(float4*)p       = make_float4(r[0], r[1], r[2], r[3]);
            *(float4*)(p + 4) = make_float4(r[4], r[5], r[6], r[7]);
        } else {                            // v
            float* p = g_v + (size_t)n * MID * HW + (size_t)(o - 1024) * HW + n0 + tx8;
            *(float4*)p       = make_float4(acc[i][0], acc[i][1], acc[i][2], acc[i][3]);
            *(float4*)(p + 4) = make_float4(acc[i][4], acc[i][5], acc[i][6], acc[i][7]);
        }
    }
}

// ---------------------------------------------------------------------------
// GEMM3: logits[x,y] = sum_d q'[d,x] * k'[d,y]   per (n, head); K=128
// ---------------------------------------------------------------------------
__global__ __launch_bounds__(256) void k_logits() {
    __shared__ float As[BK * LDS_];
    __shared__ float Bs[BK * LDS_];
    int z = blockIdx.z;              // n*4 + head
    int n = z >> 2, head = z & 3;
    int m0 = blockIdx.y * BM, n0 = blockIdx.x * BN_;
    int tid = threadIdx.x;
    int ty8 = (tid >> 4) * 8, tx8 = (tid & 15) * 8;
    const float* q = g_qk + (size_t)n * 1024 * HW + (size_t)head * DQK * HW;
    const float* k = q + (size_t)512 * HW;
    float acc[8][8] = {};
    for (int k0 = 0; k0 < DQK; k0 += BK) {
        load_tileD(As, q + (size_t)k0 * HW + m0, HW, tid);
        load_tileD(Bs, k + (size_t)k0 * HW + n0, HW, tid);
        __syncthreads();
        mma16(As, Bs, acc, ty8, tx8);
        __syncthreads();
    }
    float* out = g_logits + (size_t)z * HW * HW;
#pragma unroll
    for (int i = 0; i < 8; i++) {
        float* p = out + (size_t)(m0 + ty8 + i) * HW + n0 + tx8;
        *(float4*)p       = make_float4(acc[i][0], acc[i][1], acc[i][2], acc[i][3]);
        *(float4*)(p + 4) = make_float4(acc[i][4], acc[i][5], acc[i][6], acc[i][7]);
    }
}

// ---------------------------------------------------------------------------
// Softmax over last dim (1024) of g_logits. One block per row.
// ---------------------------------------------------------------------------
__global__ __launch_bounds__(256) void k_softmax() {
    __shared__ float red[256];
    size_t row = blockIdx.x;
    float* p = g_logits + row * HW;
    int tid = threadIdx.x;
    float4 v = *(float4*)(p + tid * 4);
    float m = fmaxf(fmaxf(v.x, v.y), fmaxf(v.z, v.w));
    red[tid] = m;
    __syncthreads();
    for (int s = 128; s > 0; s >>= 1) {
        if (tid < s) red[tid] = fmaxf(red[tid], red[tid + s]);
        __syncthreads();
    }
    float M = red[0];
    __syncthreads();
    float e0 = __expf(v.x - M), e1 = __expf(v.y - M);
    float e2 = __expf(v.z - M), e3 = __expf(v.w - M);
    red[tid] = e0 + e1 + e2 + e3;
    __syncthreads();
    for (int s = 128; s > 0; s >>= 1) {
        if (tid < s) red[tid] += red[tid + s];
        __syncthreads();
    }
    float inv = 1.f / red[0];
    *(float4*)(p + tid * 4) = make_float4(e0 * inv, e1 * inv, e2 * inv, e3 * inv);
}

// ---------------------------------------------------------------------------
// GEMM4: attn[d,x] = relu( sum_y v[d,y] * w[x,y] )   per (n, head); K=1024
// ---------------------------------------------------------------------------
__global__ __launch_bounds__(256) void k_av() {
    __shared__ float As[BK * LDS_];
    __shared__ float Bs[BK * LDS_];
    int z = blockIdx.z;
    int n = z >> 2, head = z & 3;
    int n0 = blockIdx.x * BN_;       // x tile; M(=d) covered by single 128 tile
    int tid = threadIdx.x;
    int ty8 = (tid >> 4) * 8, tx8 = (tid & 15) * 8;
    const float* vmat = g_v + (size_t)n * MID * HW + (size_t)head * DQK * HW; // [128,1024]
    const float* wmat = g_logits + (size_t)z * HW * HW;                       // [1024,1024]
    float acc[8][8] = {};
    for (int k0 = 0; k0 < HW; k0 += BK) {
        load_tileT(As, vmat + k0, HW, tid);
        load_tileT(Bs, wmat + (size_t)n0 * HW + k0, HW, tid);
        __syncthreads();
        mma16(As, Bs, acc, ty8, tx8);
        __syncthreads();
    }
    float* out = g_attn + (size_t)n * MID * HW + (size_t)head * DQK * HW;
#pragma unroll
    for (int i = 0; i < 8; i++) {
        int d = ty8 + i;
        float r[8];
#pragma unroll
        for (int j = 0; j < 8; j++) r[j] = fmaxf(acc[i][j], 0.f);
        float* p = out + (size_t)d * HW + n0 + tx8;
        *(float4*)p       = make_float4(r[0], r[1], r[2], r[3]);
        *(float4*)(p + 4) = make_float4(r[4], r[5], r[6], r[7]);
    }
}

// ---------------------------------------------------------------------------
// GEMM5: out = relu(BN(conv3_w @ attn_n) + x_n)     W[2048,512]
// ---------------------------------------------------------------------------
__global__ __launch_bounds__(256) void k_gemm3(
    const float* __restrict__ w, const float* __restrict__ gamma,
    const float* __restrict__ beta, const float* __restrict__ mean,
    const float* __restrict__ var, const float* __restrict__ x,
    float* __restrict__ out) {
    __shared__ float As[BK * LDS_];
    __shared__ float Bs[BK * LDS_];
    int n = blockIdx.z, m0 = blockIdx.y * BM, n0 = blockIdx.x * BN_;
    int tid = threadIdx.x;
    int ty8 = (tid >> 4) * 8, tx8 = (tid & 15) * 8;
    const float* a  = g_attn + (size_t)n * MID * HW + n0;
    const float* wp = w + (size_t)m0 * MID;
    float acc[8][8] = {};
    for (int k0 = 0; k0 < MID; k0 += BK) {
        load_tileT(As, wp + k0, MID, tid);
        load_tileD(Bs, a + (size_t)k0 * HW, HW, tid);
        __syncthreads();
        mma16(As, Bs, acc, ty8, tx8);
        __syncthreads();
    }
#pragma unroll
    for (int i = 0; i < 8; i++) {
        int o = m0 + ty8 + i;
        float inv  = gamma[o] * rsqrtf(var[o] + BN_EPS);
        float bias = beta[o] - mean[o] * inv;
        size_t base = (size_t)n * CIN * HW + (size_t)o * HW + n0 + tx8;
        float4 x0 = *(const float4*)(x + base);
        float4 x1 = *(const float4*)(x + base + 4);
        float xr[8] = {x0.x, x0.y, x0.z, x0.w, x1.x, x1.y, x1.z, x1.w};
        float r[8];
#pragma unroll
        for (int j = 0; j < 8; j++)
            r[j] = fmaxf(acc[i][j] * inv + bias + xr[j], 0.f);
        *(float4*)(out + base)     = make_float4(r[0], r[1], r[2], r[3]);
        *(float4*)(out + base + 4) = make_float4(r[4], r[5], r[6], r[7]);
    }
}

// ---------------------------------------------------------------------------
extern "C" void kernel_launch(void* const* d_in, const int* in_sizes, int n_in,
                              void* d_out, int out_size) {
    const float* x       = (const float*)d_in[0];
    const float* conv1_w = (const float*)d_in[1];
    const float* gamma1  = (const float*)d_in[2];
    const float* beta1   = (const float*)d_in[3];
    const float* mean1   = (const float*)d_in[4];
    const float* var1    = (const float*)d_in[5];
    const float* qk_w    = (const float*)d_in[6];
    const float* v_w     = (const float*)d_in[7];
    const float* pos_h   = (const float*)d_in[8];
    const float* pos_w   = (const float*)d_in[9];
    const float* conv3_w = (const float*)d_in[10];
    const float* gamma3  = (const float*)d_in[11];
    const float* beta3   = (const float*)d_in[12];
    const float* mean3   = (const float*)d_in[13];
    const float* var3    = (const float*)d_in[14];
    float* out = (float*)d_out;

    dim3 blk(256);
    k_gemm1 <<<dim3(8, 4, NB), blk>>>(x, conv1_w, gamma1, beta1, mean1, var1);
    k_gemm2 <<<dim3(8, 12, NB), blk>>>(qk_w, v_w, pos_h, pos_w);
    k_logits<<<dim3(8, 8, NB * NHEAD), blk>>>();
    k_softmax<<<dim3(NB * NHEAD * HW), blk>>>();
    k_av    <<<dim3(8, 1, NB * NHEAD), blk>>>();
    k_gemm3 <<<dim3(8, 16, NB), blk>>>(conv3_w, gamma3, beta3, mean3, var3, x, out);
}

// round 3
// speedup vs baseline: 2.4013x; 2.4013x over previous
#include <cuda_runtime.h>
#include <cuda_bf16.h>
#include <cstdint>
#include <cstddef>

// Problem constants
#define NB   16
#define CIN  2048
#define MID  512          // heads*dv = 4*128
#define HW   1024         // 32*32
#define DQK  128
#define NHEAD 4
#define ATT_SCALE 0.08838834764831845f   // 1/sqrt(128)
#define BN_EPS 1e-5f

// Tile config: block 128x128, K-chunk 32, 8 warps of 32(M)x64(N)
#define LDA 36
#define LDB 136

// Scratch (device globals — allocation-free kernel_launch)
__device__ float g_out1  [(size_t)NB * MID * HW];          //  33.5 MB
__device__ float g_qk    [(size_t)NB * 1024 * HW];         //  67 MB   (q' then k')
__device__ float g_v     [(size_t)NB * MID * HW];          //  33.5 MB
__device__ float g_logits[(size_t)NB * NHEAD * HW * HW];   // 268 MB
__device__ float g_attn  [(size_t)NB * MID * HW];          //  33.5 MB

// ---------------------------------------------------------------------------
__device__ __forceinline__ float f2tf(float f) {
    uint32_t u;
    asm("cvt.rna.tf32.f32 %0, %1;" : "=r"(u) : "f"(f));
    return __uint_as_float(u);
}

// A tile: [128 rows(M), 32 cols(K)] from row-major src (row stride ld)
__device__ __forceinline__ void load_A_direct(float* sA, const float* __restrict__ src,
                                              int ld, int tid) {
#pragma unroll
    for (int i = 0; i < 4; i++) {
        int g = tid + i * 256;
        int row = g >> 3, kq = (g & 7) * 4;
        float4 v = *(const float4*)(src + (size_t)row * ld + kq);
        float* p = sA + row * LDA + kq;
        p[0] = f2tf(v.x); p[1] = f2tf(v.y); p[2] = f2tf(v.z); p[3] = f2tf(v.w);
    }
}

// A tile from transposed source: src is [32 rows(K), 128 cols(M)] row-major
__device__ __forceinline__ void load_A_trans(float* sA, const float* __restrict__ src,
                                             int ld, int tid) {
#pragma unroll
    for (int i = 0; i < 4; i++) {
        int g = tid + i * 256;
        int k = g >> 5, mq = (g & 31) * 4;
        float4 v = *(const float4*)(src + (size_t)k * ld + mq);
        sA[(mq + 0) * LDA + k] = f2tf(v.x);
        sA[(mq + 1) * LDA + k] = f2tf(v.y);
        sA[(mq + 2) * LDA + k] = f2tf(v.z);
        sA[(mq + 3) * LDA + k] = f2tf(v.w);
    }
}

// B tile: [32 rows(K), 128 cols(N)] from row-major src (row stride ld)
__device__ __forceinline__ void load_B_direct(float* sB, const float* __restrict__ src,
                                              int ld, int tid) {
#pragma unroll
    for (int i = 0; i < 4; i++) {
        int g = tid + i * 256;
        int k = g >> 5, nq = (g & 31) * 4;
        float4 v = *(const float4*)(src + (size_t)k * ld + nq);
        float* p = sB + k * LDB + nq;
        p[0] = f2tf(v.x); p[1] = f2tf(v.y); p[2] = f2tf(v.z); p[3] = f2tf(v.w);
    }
}

// B tile from transposed source: src is [128 rows(N), 32 cols(K)] row-major
__device__ __forceinline__ void load_B_trans(float* sB, const float* __restrict__ src,
                                             int ld, int tid) {
#pragma unroll
    for (int i = 0; i < 4; i++) {
        int g = tid + i * 256;
        int n = g >> 3, kq = (g & 7) * 4;
        float4 v = *(const float4*)(src + (size_t)n * ld + kq);
        sB[(kq + 0) * LDB + n] = f2tf(v.x);
        sB[(kq + 1) * LDB + n] = f2tf(v.y);
        sB[(kq + 2) * LDB + n] = f2tf(v.z);
        sB[(kq + 3) * LDB + n] = f2tf(v.w);
    }
}

// One K-chunk (32) of tensor-core MMAs for this warp's 32x64 tile.
// acc[mt][nt][4]; mt: 2 m16 tiles, nt: 8 n8 tiles.
__device__ __forceinline__ void warp_mma(const float* sA, const float* sB,
                                         float acc[2][8][4],
                                         int warp_m, int warp_n, int lane) {
    int grp = lane >> 2, tg = lane & 3;
#pragma unroll
    for (int ks = 0; ks < 4; ks++) {
        int kk = ks * 8;
        uint32_t a[2][4];
#pragma unroll
        for (int mt = 0; mt < 2; mt++) {
            const float* base = sA + (warp_m + mt * 16 + grp) * LDA + kk + tg;
            a[mt][0] = __float_as_uint(base[0]);
            a[mt][1] = __float_as_uint(base[8 * LDA]);
            a[mt][2] = __float_as_uint(base[4]);
            a[mt][3] = __float_as_uint(base[8 * LDA + 4]);
        }
#pragma unroll
        for (int nt = 0; nt < 8; nt++) {
            const float* bb = sB + (kk + tg) * LDB + warp_n + nt * 8 + grp;
            uint32_t b0 = __float_as_uint(bb[0]);
            uint32_t b1 = __float_as_uint(bb[4 * LDB]);
#pragma unroll
            for (int mt = 0; mt < 2; mt++) {
                asm volatile(
                    "mma.sync.aligned.m16n8k8.row.col.f32.tf32.tf32.f32 "
                    "{%0,%1,%2,%3}, {%4,%5,%6,%7}, {%8,%9}, {%0,%1,%2,%3};\n"
                    : "+f"(acc[mt][nt][0]), "+f"(acc[mt][nt][1]),
                      "+f"(acc[mt][nt][2]), "+f"(acc[mt][nt][3])
                    : "r"(a[mt][0]), "r"(a[mt][1]), "r"(a[mt][2]), "r"(a[mt][3]),
                      "r"(b0), "r"(b1));
            }
        }
    }
}

// Per-thread output coordinates for fragment (mt, nt):
//   rows: r0 = warp_m + mt*16 + grp (acc 0,1), r1 = r0 + 8 (acc 2,3)
//   cols: c  = warp_n + nt*8 + 2*tg (acc 0,2), c+1 (acc 1,3)

// ---------------------------------------------------------------------------
// GEMM1: out1 = relu(BN(conv1_w @ x_n))   M=512, K=2048, N=1024
// ---------------------------------------------------------------------------
__global__ __launch_bounds__(256, 2) void k_gemm1(
    const float* __restrict__ x, const float* __restrict__ w,
    const float* __restrict__ gamma, const float* __restrict__ beta,
    const float* __restrict__ mean, const float* __restrict__ var) {
    __shared__ float sA[128 * LDA];
    __shared__ float sB[32 * LDB];
    int n = blockIdx.z, m0 = blockIdx.y * 128, n0 = blockIdx.x * 128;
    int tid = threadIdx.x, lane = tid & 31, warp = tid >> 5;
    int warp_m = (warp & 3) * 32, warp_n = (warp >> 2) * 64;
    int grp = lane >> 2, tg = lane & 3;
    const float* wp = w + (size_t)m0 * CIN;
    const float* xp = x + (size_t)n * CIN * HW + n0;
    float acc[2][8][4] = {};
    for (int k0 = 0; k0 < CIN; k0 += 32) {
        load_A_direct(sA, wp + k0, CIN, tid);
        load_B_direct(sB, xp + (size_t)k0 * HW, HW, tid);
        __syncthreads();
        warp_mma(sA, sB, acc, warp_m, warp_n, lane);
        __syncthreads();
    }
    float* outb = g_out1 + (size_t)n * MID * HW;
#pragma unroll
    for (int mt = 0; mt < 2; mt++) {
        int o0 = m0 + warp_m + mt * 16 + grp, o1 = o0 + 8;
        float inv0 = gamma[o0] * rsqrtf(var[o0] + BN_EPS);
        float bi0  = beta[o0] - mean[o0] * inv0;
        float inv1 = gamma[o1] * rsqrtf(var[o1] + BN_EPS);
        float bi1  = beta[o1] - mean[o1] * inv1;
#pragma unroll
        for (int nt = 0; nt < 8; nt++) {
            int c = n0 + warp_n + nt * 8 + 2 * tg;
            float* a4 = acc[mt][nt];
            *(float2*)(outb + (size_t)o0 * HW + c) =
                make_float2(fmaxf(a4[0] * inv0 + bi0, 0.f), fmaxf(a4[1] * inv0 + bi0, 0.f));
            *(float2*)(outb + (size_t)o1 * HW + c) =
                make_float2(fmaxf(a4[2] * inv1 + bi1, 0.f), fmaxf(a4[3] * inv1 + bi1, 0.f));
        }
    }
}

// ---------------------------------------------------------------------------
// GEMM2: [q;k;v] projections   M=1536, K=512, N=1024
// ---------------------------------------------------------------------------
__global__ __launch_bounds__(256, 2) void k_gemm2(
    const float* __restrict__ qk_w, const float* __restrict__ v_w,
    const float* __restrict__ pos_h, const float* __restrict__ pos_w) {
    __shared__ float sA[128 * LDA];
    __shared__ float sB[32 * LDB];
    int n = blockIdx.z, m0 = blockIdx.y * 128, n0 = blockIdx.x * 128;
    int tid = threadIdx.x, lane = tid & 31, warp = tid >> 5;
    int warp_m = (warp & 3) * 32, warp_n = (warp >> 2) * 64;
    int grp = lane >> 2, tg = lane & 3;
    const float* wp = (m0 < 1024) ? qk_w + (size_t)m0 * MID
                                  : v_w + (size_t)(m0 - 1024) * MID;
    const float* ap = g_out1 + (size_t)n * MID * HW + n0;
    float acc[2][8][4] = {};
    for (int k0 = 0; k0 < MID; k0 += 32) {
        load_A_direct(sA, wp + k0, MID, tid);
        load_B_direct(sB, ap + (size_t)k0 * HW, HW, tid);
        __syncthreads();
        warp_mma(sA, sB, acc, warp_m, warp_n, lane);
        __syncthreads();
    }
#pragma unroll
    for (int mt = 0; mt < 2; mt++) {
        int o0 = m0 + warp_m + mt * 16 + grp;
#pragma unroll
        for (int half = 0; half < 2; half++) {   // half=0 -> acc[0,1] row o0; half=1 -> acc[2,3] row o0+8
            int o = o0 + half * 8;
#pragma unroll
            for (int nt = 0; nt < 8; nt++) {
                int c = n0 + warp_n + nt * 8 + 2 * tg;
                float v0 = acc[mt][nt][half * 2 + 0];
                float v1 = acc[mt][nt][half * 2 + 1];
                if (o < 512) {                       // q' = q * scale
                    float* p = g_qk + (size_t)n * 1024 * HW + (size_t)o * HW + c;
                    *(float2*)p = make_float2(v0 * ATT_SCALE, v1 * ATT_SCALE);
                } else if (o < 1024) {               // k' = k + emb[y, d]
                    int d = (o - 512) & 127;
                    int hh = c >> 5, ww = c & 31;
                    float ph = pos_h[hh * DQK + d];
                    float e0 = ph + pos_w[ww * DQK + d];
                    float e1 = ph + pos_w[(ww + 1) * DQK + d];
                    float* p = g_qk + (size_t)n * 1024 * HW + (size_t)o * HW + c;
                    *(float2*)p = make_float2(v0 + e0, v1 + e1);
                } else {                             // v
                    float* p = g_v + (size_t)n * MID * HW + (size_t)(o - 1024) * HW + c;
                    *(float2*)p = make_float2(v0, v1);
                }
            }
        }
    }
}

// ---------------------------------------------------------------------------
// Logits: L[x,y] = sum_d q'[d,x] * k'[d,y]   per (n, head); K=128
// ---------------------------------------------------------------------------
__global__ __launch_bounds__(256, 2) void k_logits() {
    __shared__ float sA[128 * LDA];
    __shared__ float sB[32 * LDB];
    int z = blockIdx.z;              // n*4 + head
    int n = z >> 2, head = z & 3;
    int m0 = blockIdx.y * 128, n0 = blockIdx.x * 128;
    int tid = threadIdx.x, lane = tid & 31, warp = tid >> 5;
    int warp_m = (warp & 3) * 32, warp_n = (warp >> 2) * 64;
    int grp = lane >> 2, tg = lane & 3;
    const float* q = g_qk + (size_t)n * 1024 * HW + (size_t)head * DQK * HW;
    const float* k = q + (size_t)512 * HW;
    float acc[2][8][4] = {};
    for (int k0 = 0; k0 < DQK; k0 += 32) {
        load_A_trans(sA, q + (size_t)k0 * HW + m0, HW, tid);
        load_B_direct(sB, k + (size_t)k0 * HW + n0, HW, tid);
        __syncthreads();
        warp_mma(sA, sB, acc, warp_m, warp_n, lane);
        __syncthreads();
    }
    float* out = g_logits + (size_t)z * HW * HW;
#pragma unroll
    for (int mt = 0; mt < 2; mt++) {
        int r0 = m0 + warp_m + mt * 16 + grp, r1 = r0 + 8;
#pragma unroll
        for (int nt = 0; nt < 8; nt++) {
            int c = n0 + warp_n + nt * 8 + 2 * tg;
            float* a4 = acc[mt][nt];
            *(float2*)(out + (size_t)r0 * HW + c) = make_float2(a4[0], a4[1]);
            *(float2*)(out + (size_t)r1 * HW + c) = make_float2(a4[2], a4[3]);
        }
    }
}

// ---------------------------------------------------------------------------
// Softmax over last dim (1024). One block per row.
// ---------------------------------------------------------------------------
__global__ __launch_bounds__(256) void k_softmax() {
    __shared__ float red[256];
    size_t row = blockIdx.x;
    float* p = g_logits + row * HW;
    int tid = threadIdx.x;
    float4 v = *(float4*)(p + tid * 4);
    float m = fmaxf(fmaxf(v.x, v.y), fmaxf(v.z, v.w));
    red[tid] = m;
    __syncthreads();
    for (int s = 128; s > 0; s >>= 1) {
        if (tid < s) red[tid] = fmaxf(red[tid], red[tid + s]);
        __syncthreads();
    }
    float M = red[0];
    __syncthreads();
    float e0 = __expf(v.x - M), e1 = __expf(v.y - M);
    float e2 = __expf(v.z - M), e3 = __expf(v.w - M);
    red[tid] = e0 + e1 + e2 + e3;
    __syncthreads();
    for (int s = 128; s > 0; s >>= 1) {
        if (tid < s) red[tid] += red[tid + s];
        __syncthreads();
    }
    float inv = 1.f / red[0];
    *(float4*)(p + tid * 4) = make_float4(e0 * inv, e1 * inv, e2 * inv, e3 * inv);
}

// ---------------------------------------------------------------------------
// AV: attn[d,x] = relu( sum_y V[d,y] * P[x,y] )   per (n, head); K=1024
// ---------------------------------------------------------------------------
__global__ __launch_bounds__(256, 2) void k_av() {
    __shared__ float sA[128 * LDA];
    __shared__ float sB[32 * LDB];
    int z = blockIdx.z;
    int n = z >> 2, head = z & 3;
    int n0 = blockIdx.x * 128;       // x tile; d covered by single 128 tile
    int tid = threadIdx.x, lane = tid & 31, warp = tid >> 5;
    int warp_m = (warp & 3) * 32, warp_n = (warp >> 2) * 64;
    int grp = lane >> 2, tg = lane & 3;
    const float* vmat = g_v + (size_t)n * MID * HW + (size_t)head * DQK * HW; // [128,1024]
    const float* wmat = g_logits + (size_t)z * HW * HW;                       // [1024,1024]
    float acc[2][8][4] = {};
    for (int k0 = 0; k0 < HW; k0 += 32) {
        load_A_direct(sA, vmat + k0, HW, tid);
        load_B_trans(sB, wmat + (size_t)n0 * HW + k0, HW, tid);
        __syncthreads();
        warp_mma(sA, sB, acc, warp_m, warp_n, lane);
        __syncthreads();
    }
    float* out = g_attn + (size_t)n * MID * HW + (size_t)head * DQK * HW;
#pragma unroll
    for (int mt = 0; mt < 2; mt++) {
        int r0 = warp_m + mt * 16 + grp, r1 = r0 + 8;
#pragma unroll
        for (int nt = 0; nt < 8; nt++) {
            int c = n0 + warp_n + nt * 8 + 2 * tg;
            float* a4 = acc[mt][nt];
            *(float2*)(out + (size_t)r0 * HW + c) =
                make_float2(fmaxf(a4[0], 0.f), fmaxf(a4[1], 0.f));
            *(float2*)(out + (size_t)r1 * HW + c) =
                make_float2(fmaxf(a4[2], 0.f), fmaxf(a4[3], 0.f));
        }
    }
}

// ---------------------------------------------------------------------------
// GEMM3: out = relu(BN(conv3_w @ attn_n) + x_n)   M=2048, K=512, N=1024
// ---------------------------------------------------------------------------
__global__ __launch_bounds__(256, 2) void k_gemm3(
    const float* __restrict__ w, const float* __restrict__ gamma,
    const float* __restrict__ beta, const float* __restrict__ mean,
    const float* __restrict__ var, const float* __restrict__ x,
    float* __restrict__ out) {
    __shared__ float sA[128 * LDA];
    __shared__ float sB[32 * LDB];
    int n = blockIdx.z, m0 = blockIdx.y * 128, n0 = blockIdx.x * 128;
    int tid = threadIdx.x, lane = tid & 31, warp = tid >> 5;
    int warp_m = (warp & 3) * 32, warp_n = (warp >> 2) * 64;
    int grp = lane >> 2, tg = lane & 3;
    const float* wp = w + (size_t)m0 * MID;
    const float* ap = g_attn + (size_t)n * MID * HW + n0;
    float acc[2][8][4] = {};
    for (int k0 = 0; k0 < MID; k0 += 32) {
        load_A_direct(sA, wp + k0, MID, tid);
        load_B_direct(sB, ap + (size_t)k0 * HW, HW, tid);
        __syncthreads();
        warp_mma(sA, sB, acc, warp_m, warp_n, lane);
        __syncthreads();
    }
#pragma unroll
    for (int mt = 0; mt < 2; mt++) {
        int o0 = m0 + warp_m + mt * 16 + grp, o1 = o0 + 8;
        float inv0 = gamma[o0] * rsqrtf(var[o0] + BN_EPS);
        float bi0  = beta[o0] - mean[o0] * inv0;
        float inv1 = gamma[o1] * rsqrtf(var[o1] + BN_EPS);
        float bi1  = beta[o1] - mean[o1] * inv1;
#pragma unroll
        for (int nt = 0; nt < 8; nt++) {
            int c = n0 + warp_n + nt * 8 + 2 * tg;
            float* a4 = acc[mt][nt];
            size_t b0 = (size_t)n * CIN * HW + (size_t)o0 * HW + c;
            size_t b1 = (size_t)n * CIN * HW + (size_t)o1 * HW + c;
            float2 x0 = *(const float2*)(x + b0);
            float2 x1 = *(const float2*)(x + b1);
            *(float2*)(out + b0) = make_float2(
                fmaxf(a4[0] * inv0 + bi0 + x0.x, 0.f),
                fmaxf(a4[1] * inv0 + bi0 + x0.y, 0.f));
            *(float2*)(out + b1) = make_float2(
                fmaxf(a4[2] * inv1 + bi1 + x1.x, 0.f),
                fmaxf(a4[3] * inv1 + bi1 + x1.y, 0.f));
        }
    }
}

// ---------------------------------------------------------------------------
extern "C" void kernel_launch(void* const* d_in, const int* in_sizes, int n_in,
                              void* d_out, int out_size) {
    const float* x       = (const float*)d_in[0];
    const float* conv1_w = (const float*)d_in[1];
    const float* gamma1  = (const float*)d_in[2];
    const float* beta1   = (const float*)d_in[3];
    const float* mean1   = (const float*)d_in[4];
    const float* var1    = (const float*)d_in[5];
    const float* qk_w    = (const float*)d_in[6];
    const float* v_w     = (const float*)d_in[7];
    const float* pos_h   = (const float*)d_in[8];
    const float* pos_w   = (const float*)d_in[9];
    const float* conv3_w = (const float*)d_in[10];
    const float* gamma3  = (const float*)d_in[11];
    const float* beta3   = (const float*)d_in[12];
    const float* mean3   = (const float*)d_in[13];
    const float* var3    = (const float*)d_in[14];
    float* out = (float*)d_out;

    dim3 blk(256);
    k_gemm1 <<<dim3(8, 4, NB), blk>>>(x, conv1_w, gamma1, beta1, mean1, var1);
    k_gemm2 <<<dim3(8, 12, NB), blk>>>(qk_w, v_w, pos_h, pos_w);
    k_logits<<<dim3(8, 8, NB * NHEAD), blk>>>();
    k_softmax<<<dim3(NB * NHEAD * HW), blk>>>();
    k_av    <<<dim3(8, 1, NB * NHEAD), blk>>>();
    k_gemm3 <<<dim3(8, 16, NB), blk>>>(conv3_w, gamma3, beta3, mean3, var3, x, out);
}

// round 4
// speedup vs baseline: 2.5991x; 1.0824x over previous
#include <cuda_runtime.h>
#include <cuda_bf16.h>
#include <cstdint>
#include <cstddef>

// Problem constants
#define NB   16
#define CIN  2048
#define MID  512          // heads*dv = 4*128
#define HW   1024         // 32*32
#define DQK  128
#define NHEAD 4
#define ATT_SCALE 0.08838834764831845f   // 1/sqrt(128)
#define BN_EPS 1e-5f

// GEMM tile config: block 128x128, K-chunk 32, 8 warps of 32(M)x64(N)
#define LDA 36
#define LDB 136

// Flash tile config
#define FX 64             // x rows per block
#define LDQ 132           // row stride for Qs / Ss (132 % 32 == 4 -> conflict-free frags)
#define Q_ELE (FX * LDQ)                   // 8448 floats
#define S_OFF Q_ELE
#define B_OFF (2 * Q_ELE)
#define MB_OFF (B_OFF + 32 * LDB)
#define LB_OFF (MB_OFF + FX)
#define SC_OFF (LB_OFF + FX)
#define FLASH_SMEM ((SC_OFF + FX) * 4)     // ~85.8 KB

// Scratch (device globals — allocation-free kernel_launch)
__device__ float g_out1[(size_t)NB * MID * HW];           // 33.5 MB
__device__ float g_qk  [(size_t)NB * 1024 * HW];          // 67 MB   (q' then k')
__device__ float g_v   [(size_t)NB * MID * HW];           // 33.5 MB
__device__ float g_attn[(size_t)NB * MID * HW];           // 33.5 MB

// ---------------------------------------------------------------------------
__device__ __forceinline__ float f2tf(float f) {
    uint32_t u;
    asm("cvt.rna.tf32.f32 %0, %1;" : "=r"(u) : "f"(f));
    return __uint_as_float(u);
}

// A tile: [128 rows(M), 32 cols(K)] from row-major src (row stride ld)
__device__ __forceinline__ void load_A_direct(float* sA, const float* __restrict__ src,
                                              int ld, int tid) {
#pragma unroll
    for (int i = 0; i < 4; i++) {
        int g = tid + i * 256;
        int row = g >> 3, kq = (g & 7) * 4;
        float4 v = *(const float4*)(src + (size_t)row * ld + kq);
        float* p = sA + row * LDA + kq;
        p[0] = f2tf(v.x); p[1] = f2tf(v.y); p[2] = f2tf(v.z); p[3] = f2tf(v.w);
    }
}

// B tile: [32 rows(K), 128 cols(N)] from row-major src (row stride ld)
__device__ __forceinline__ void load_B_direct(float* sB, const float* __restrict__ src,
                                              int ld, int tid) {
#pragma unroll
    for (int i = 0; i < 4; i++) {
        int g = tid + i * 256;
        int k = g >> 5, nq = (g & 31) * 4;
        float4 v = *(const float4*)(src + (size_t)k * ld + nq);
        float* p = sB + k * LDB + nq;
        p[0] = f2tf(v.x); p[1] = f2tf(v.y); p[2] = f2tf(v.z); p[3] = f2tf(v.w);
    }
}

// B tile from transposed source: src is [128 rows(N), 32 cols(K)] row-major
__device__ __forceinline__ void load_B_trans(float* sB, const float* __restrict__ src,
                                             int ld, int tid) {
#pragma unroll
    for (int i = 0; i < 4; i++) {
        int g = tid + i * 256;
        int n = g >> 3, kq = (g & 7) * 4;
        float4 v = *(const float4*)(src + (size_t)n * ld + kq);
        sB[(kq + 0) * LDB + n] = f2tf(v.x);
        sB[(kq + 1) * LDB + n] = f2tf(v.y);
        sB[(kq + 2) * LDB + n] = f2tf(v.z);
        sB[(kq + 3) * LDB + n] = f2tf(v.w);
    }
}

// One K-chunk (32) of MMAs, warp tile 32(M) x 64(N): acc[2][8][4]
__device__ __forceinline__ void warp_mma(const float* sA, const float* sB,
                                         float acc[2][8][4],
                                         int warp_m, int warp_n, int lane) {
    int grp = lane >> 2, tg = lane & 3;
#pragma unroll
    for (int ks = 0; ks < 4; ks++) {
        int kk = ks * 8;
        uint32_t a[2][4];
#pragma unroll
        for (int mt = 0; mt < 2; mt++) {
            const float* base = sA + (warp_m + mt * 16 + grp) * LDA + kk + tg;
            a[mt][0] = __float_as_uint(base[0]);
            a[mt][1] = __float_as_uint(base[8 * LDA]);
            a[mt][2] = __float_as_uint(base[4]);
            a[mt][3] = __float_as_uint(base[8 * LDA + 4]);
        }
#pragma unroll
        for (int nt = 0; nt < 8; nt++) {
            const float* bb = sB + (kk + tg) * LDB + warp_n + nt * 8 + grp;
            uint32_t b0 = __float_as_uint(bb[0]);
            uint32_t b1 = __float_as_uint(bb[4 * LDB]);
#pragma unroll
            for (int mt = 0; mt < 2; mt++) {
                asm volatile(
                    "mma.sync.aligned.m16n8k8.row.col.f32.tf32.tf32.f32 "
                    "{%0,%1,%2,%3}, {%4,%5,%6,%7}, {%8,%9}, {%0,%1,%2,%3};\n"
                    : "+f"(acc[mt][nt][0]), "+f"(acc[mt][nt][1]),
                      "+f"(acc[mt][nt][2]), "+f"(acc[mt][nt][3])
                    : "r"(a[mt][0]), "r"(a[mt][1]), "r"(a[mt][2]), "r"(a[mt][3]),
                      "r"(b0), "r"(b1));
            }
        }
    }
}

// Flash variant: warp tile 32(M) x 32(N), A row stride LDQ: acc[2][4][4]
__device__ __forceinline__ void warp_mma_f(const float* A, const float* sB,
                                           float acc[2][4][4],
                                           int wm, int wn, int lane) {
    int grp = lane >> 2, tg = lane & 3;
#pragma unroll
    for (int ks = 0; ks < 4; ks++) {
        int kk = ks * 8;
        uint32_t a[2][4];
#pragma unroll
        for (int mt = 0; mt < 2; mt++) {
            const float* base = A + (wm + mt * 16 + grp) * LDQ + kk + tg;
            a[mt][0] = __float_as_uint(base[0]);
            a[mt][1] = __float_as_uint(base[8 * LDQ]);
            a[mt][2] = __float_as_uint(base[4]);
            a[mt][3] = __float_as_uint(base[8 * LDQ + 4]);
        }
#pragma unroll
        for (int nt = 0; nt < 4; nt++) {
            const float* bb = sB + (kk + tg) * LDB + wn + nt * 8 + grp;
            uint32_t b0 = __float_as_uint(bb[0]);
            uint32_t b1 = __float_as_uint(bb[4 * LDB]);
#pragma unroll
            for (int mt = 0; mt < 2; mt++) {
                asm volatile(
                    "mma.sync.aligned.m16n8k8.row.col.f32.tf32.tf32.f32 "
                    "{%0,%1,%2,%3}, {%4,%5,%6,%7}, {%8,%9}, {%0,%1,%2,%3};\n"
                    : "+f"(acc[mt][nt][0]), "+f"(acc[mt][nt][1]),
                      "+f"(acc[mt][nt][2]), "+f"(acc[mt][nt][3])
                    : "r"(a[mt][0]), "r"(a[mt][1]), "r"(a[mt][2]), "r"(a[mt][3]),
                      "r"(b0), "r"(b1));
            }
        }
    }
}

// ---------------------------------------------------------------------------
// GEMM1: out1 = relu(BN(conv1_w @ x_n))   M=512, K=2048, N=1024
// ---------------------------------------------------------------------------
__global__ __launch_bounds__(256, 2) void k_gemm1(
    const float* __restrict__ x, const float* __restrict__ w,
    const float* __restrict__ gamma, const float* __restrict__ beta,
    const float* __restrict__ mean, const float* __restrict__ var) {
    __shared__ float sA[128 * LDA];
    __shared__ float sB[32 * LDB];
    int n = blockIdx.z, m0 = blockIdx.y * 128, n0 = blockIdx.x * 128;
    int tid = threadIdx.x, lane = tid & 31, warp = tid >> 5;
    int warp_m = (warp & 3) * 32, warp_n = (warp >> 2) * 64;
    int grp = lane >> 2, tg = lane & 3;
    const float* wp = w + (size_t)m0 * CIN;
    const float* xp = x + (size_t)n * CIN * HW + n0;
    float acc[2][8][4] = {};
    for (int k0 = 0; k0 < CIN; k0 += 32) {
        load_A_direct(sA, wp + k0, CIN, tid);
        load_B_direct(sB, xp + (size_t)k0 * HW, HW, tid);
        __syncthreads();
        warp_mma(sA, sB, acc, warp_m, warp_n, lane);
        __syncthreads();
    }
    float* outb = g_out1 + (size_t)n * MID * HW;
#pragma unroll
    for (int mt = 0; mt < 2; mt++) {
        int o0 = m0 + warp_m + mt * 16 + grp, o1 = o0 + 8;
        float inv0 = gamma[o0] * rsqrtf(var[o0] + BN_EPS);
        float bi0  = beta[o0] - mean[o0] * inv0;
        float inv1 = gamma[o1] * rsqrtf(var[o1] + BN_EPS);
        float bi1  = beta[o1] - mean[o1] * inv1;
#pragma unroll
        for (int nt = 0; nt < 8; nt++) {
            int c = n0 + warp_n + nt * 8 + 2 * tg;
            float* a4 = acc[mt][nt];
            *(float2*)(outb + (size_t)o0 * HW + c) =
                make_float2(fmaxf(a4[0] * inv0 + bi0, 0.f), fmaxf(a4[1] * inv0 + bi0, 0.f));
            *(float2*)(outb + (size_t)o1 * HW + c) =
                make_float2(fmaxf(a4[2] * inv1 + bi1, 0.f), fmaxf(a4[3] * inv1 + bi1, 0.f));
        }
    }
}

// ---------------------------------------------------------------------------
// GEMM2: [q;k;v] projections   M=1536, K=512, N=1024
// ---------------------------------------------------------------------------
__global__ __launch_bounds__(256, 2) void k_gemm2(
    const float* __restrict__ qk_w, const float* __restrict__ v_w,
    const float* __restrict__ pos_h, const float* __restrict__ pos_w) {
    __shared__ float sA[128 * LDA];
    __shared__ float sB[32 * LDB];
    int n = blockIdx.z, m0 = blockIdx.y * 128, n0 = blockIdx.x * 128;
    int tid = threadIdx.x, lane = tid & 31, warp = tid >> 5;
    int warp_m = (warp & 3) * 32, warp_n = (warp >> 2) * 64;
    int grp = lane >> 2, tg = lane & 3;
    const float* wp = (m0 < 1024) ? qk_w + (size_t)m0 * MID
                                  : v_w + (size_t)(m0 - 1024) * MID;
    const float* ap = g_out1 + (size_t)n * MID * HW + n0;
    float acc[2][8][4] = {};
    for (int k0 = 0; k0 < MID; k0 += 32) {
        load_A_direct(sA, wp + k0, MID, tid);
        load_B_direct(sB, ap + (size_t)k0 * HW, HW, tid);
        __syncthreads();
        warp_mma(sA, sB, acc, warp_m, warp_n, lane);
        __syncthreads();
    }
#pragma unroll
    for (int mt = 0; mt < 2; mt++) {
        int o0 = m0 + warp_m + mt * 16 + grp;
#pragma unroll
        for (int half = 0; half < 2; half++) {
            int o = o0 + half * 8;
#pragma unroll
            for (int nt = 0; nt < 8; nt++) {
                int c = n0 + warp_n + nt * 8 + 2 * tg;
                float v0 = acc[mt][nt][half * 2 + 0];
                float v1 = acc[mt][nt][half * 2 + 1];
                if (o < 512) {                       // q' = q * scale
                    float* p = g_qk + (size_t)n * 1024 * HW + (size_t)o * HW + c;
                    *(float2*)p = make_float2(v0 * ATT_SCALE, v1 * ATT_SCALE);
                } else if (o < 1024) {               // k' = k + emb[y, d]
                    int d = (o - 512) & 127;
                    int hh = c >> 5, ww = c & 31;
                    float ph = pos_h[hh * DQK + d];
                    float e0 = ph + pos_w[ww * DQK + d];
                    float e1 = ph + pos_w[(ww + 1) * DQK + d];
                    float* p = g_qk + (size_t)n * 1024 * HW + (size_t)o * HW + c;
                    *(float2*)p = make_float2(v0 + e0, v1 + e1);
                } else {                             // v
                    float* p = g_v + (size_t)n * MID * HW + (size_t)(o - 1024) * HW + c;
                    *(float2*)p = make_float2(v0, v1);
                }
            }
        }
    }
}

// ---------------------------------------------------------------------------
// Fused flash attention: per (n, head, x-tile of 64):
//   S = Q'^T K'  (scale/emb pre-folded), online softmax, O = P V^T, relu,
//   transposed store to g_attn [d, x].
// ---------------------------------------------------------------------------
__global__ __launch_bounds__(256, 2) void k_flash() {
    extern __shared__ float sm[];
    float* Qs    = sm;                // [FX][LDQ]  (x, d)
    float* Ss    = sm + S_OFF;        // [FX][LDQ]  (x, y) then (x, d)
    float* sB    = sm + B_OFF;        // [32][LDB]
    float* sm_m  = sm + MB_OFF;
    float* sm_l  = sm + LB_OFF;
    float* sm_sc = sm + SC_OFF;

    int z = blockIdx.z;               // n*4 + head
    int n = z >> 2, head = z & 3;
    int x0 = blockIdx.x * FX;
    int tid = threadIdx.x, lane = tid & 31, warp = tid >> 5;
    int wm = (warp & 1) * 32, wn = (warp >> 1) * 32;
    int grp = lane >> 2, tg = lane & 3;

    const float* qp = g_qk + (size_t)n * 1024 * HW + (size_t)head * DQK * HW; // [128 d][1024 x]
    const float* kp = qp + (size_t)512 * HW;
    const float* vp = g_v + (size_t)n * MID * HW + (size_t)head * DQK * HW;   // [128 d][1024 y]

    // Load Q tile [64 x][128 d], transposing from [d][x] source
#pragma unroll
    for (int i = 0; i < 8; i++) {
        int g = tid + i * 256;                 // 2048 float4s = 128 d * 16
        int d = g >> 4, xq = (g & 15) * 4;
        float4 v = *(const float4*)(qp + (size_t)d * HW + x0 + xq);
        Qs[(xq + 0) * LDQ + d] = f2tf(v.x);
        Qs[(xq + 1) * LDQ + d] = f2tf(v.y);
        Qs[(xq + 2) * LDQ + d] = f2tf(v.z);
        Qs[(xq + 3) * LDQ + d] = f2tf(v.w);
    }
    if (tid < FX) { sm_m[tid] = -1e30f; sm_l[tid] = 0.f; }
    float acc_o[2][4][4] = {};
    float acc_s[2][4][4] = {};
    __syncthreads();

    for (int j = 0; j < 8; j++) {
        int y0 = j * 128;
        // ---- S = Q @ K'^T  (K-dim = d, 4 chunks of 32) ----
        for (int c = 0; c < 4; c++) {
            __syncthreads();
            load_B_direct(sB, kp + (size_t)(c * 32) * HW + y0, HW, tid);
            __syncthreads();
            warp_mma_f(Qs + c * 32, sB, acc_s, wm, wn, lane);
        }
        // ---- write S tile to Ss, zero acc_s ----
        __syncthreads();
#pragma unroll
        for (int mt = 0; mt < 2; mt++) {
            int r0 = wm + mt * 16 + grp, r1 = r0 + 8;
#pragma unroll
            for (int nt = 0; nt < 4; nt++) {
                int c = wn + nt * 8 + 2 * tg;
                Ss[r0 * LDQ + c]     = acc_s[mt][nt][0];
                Ss[r0 * LDQ + c + 1] = acc_s[mt][nt][1];
                Ss[r1 * LDQ + c]     = acc_s[mt][nt][2];
                Ss[r1 * LDQ + c + 1] = acc_s[mt][nt][3];
                acc_s[mt][nt][0] = acc_s[mt][nt][1] = 0.f;
                acc_s[mt][nt][2] = acc_s[mt][nt][3] = 0.f;
            }
        }
        __syncthreads();
        // ---- online softmax: 4 threads per row, stride-4 cols (conflict-free) ----
        {
            int r = tid >> 2, q = tid & 3;
            float* row = Ss + r * LDQ;
            float mloc = -1e30f;
#pragma unroll
            for (int i = 0; i < 32; i++) mloc = fmaxf(mloc, row[q + 4 * i]);
            mloc = fmaxf(mloc, __shfl_xor_sync(0xffffffff, mloc, 1));
            mloc = fmaxf(mloc, __shfl_xor_sync(0xffffffff, mloc, 2));
            float m_old = sm_m[r];
            float m_new = fmaxf(m_old, mloc);
            float s = 0.f;
#pragma unroll
            for (int i = 0; i < 32; i++) {
                float p = __expf(row[q + 4 * i] - m_new);
                row[q + 4 * i] = f2tf(p);
                s += p;
            }
            s += __shfl_xor_sync(0xffffffff, s, 1);
            s += __shfl_xor_sync(0xffffffff, s, 2);
            if (q == 0) {
                sm_sc[r] = __expf(m_old - m_new);
                sm_m[r]  = m_new;
                sm_l[r]  = sm_l[r] * sm_sc[r] + s;
            }
        }
        __syncthreads();
        // ---- rescale O accumulator ----
#pragma unroll
        for (int mt = 0; mt < 2; mt++) {
            int r0 = wm + mt * 16 + grp;
            float s0 = sm_sc[r0], s1 = sm_sc[r0 + 8];
#pragma unroll
            for (int nt = 0; nt < 4; nt++) {
                acc_o[mt][nt][0] *= s0; acc_o[mt][nt][1] *= s0;
                acc_o[mt][nt][2] *= s1; acc_o[mt][nt][3] *= s1;
            }
        }
        // ---- O += P @ V^T  (K-dim = y, 4 chunks of 32) ----
        for (int c = 0; c < 4; c++) {
            __syncthreads();
            load_B_trans(sB, vp + y0 + c * 32, HW, tid);
            __syncthreads();
            warp_mma_f(Ss + c * 32, sB, acc_o, wm, wn, lane);
        }
    }

    // ---- epilogue: O /= l, relu, transpose via Ss, coalesced store ----
    __syncthreads();
#pragma unroll
    for (int mt = 0; mt < 2; mt++) {
        int r0 = wm + mt * 16 + grp, r1 = r0 + 8;
        float l0 = 1.f / sm_l[r0], l1 = 1.f / sm_l[r1];
#pragma unroll
        for (int nt = 0; nt < 4; nt++) {
            int c = wn + nt * 8 + 2 * tg;
            Ss[r0 * LDQ + c]     = fmaxf(acc_o[mt][nt][0] * l0, 0.f);
            Ss[r0 * LDQ + c + 1] = fmaxf(acc_o[mt][nt][1] * l0, 0.f);
            Ss[r1 * LDQ + c]     = fmaxf(acc_o[mt][nt][2] * l1, 0.f);
            Ss[r1 * LDQ + c + 1] = fmaxf(acc_o[mt][nt][3] * l1, 0.f);
        }
    }
    __syncthreads();
    float* op = g_attn + (size_t)n * MID * HW + (size_t)head * DQK * HW;
#pragma unroll
    for (int i = 0; i < 32; i++) {
        int g = tid + i * 256;                 // 8192 = 128 d * 64 x
        int d = g >> 6, xo = g & 63;
        op[(size_t)d * HW + x0 + xo] = Ss[xo * LDQ + d];
    }
}

// ---------------------------------------------------------------------------
// GEMM3: out = relu(BN(conv3_w @ attn_n) + x_n)   M=2048, K=512, N=1024
// ---------------------------------------------------------------------------
__global__ __launch_bounds__(256, 2) void k_gemm3(
    const float* __restrict__ w, const float* __restrict__ gamma,
    const float* __restrict__ beta, const float* __restrict__ mean,
    const float* __restrict__ var, const float* __restrict__ x,
    float* __restrict__ out) {
    __shared__ float sA[128 * LDA];
    __shared__ float sB[32 * LDB];
    int n = blockIdx.z, m0 = blockIdx.y * 128, n0 = blockIdx.x * 128;
    int tid = threadIdx.x, lane = tid & 31, warp = tid >> 5;
    int warp_m = (warp & 3) * 32, warp_n = (warp >> 2) * 64;
    int grp = lane >> 2, tg = lane & 3;
    const float* wp = w + (size_t)m0 * MID;
    const float* ap = g_attn + (size_t)n * MID * HW + n0;
    float acc[2][8][4] = {};
    for (int k0 = 0; k0 < MID; k0 += 32) {
        load_A_direct(sA, wp + k0, MID, tid);
        load_B_direct(sB, ap + (size_t)k0 * HW, HW, tid);
        __syncthreads();
        warp_mma(sA, sB, acc, warp_m, warp_n, lane);
        __syncthreads();
    }
#pragma unroll
    for (int mt = 0; mt < 2; mt++) {
        int o0 = m0 + warp_m + mt * 16 + grp, o1 = o0 + 8;
        float inv0 = gamma[o0] * rsqrtf(var[o0] + BN_EPS);
        float bi0  = beta[o0] - mean[o0] * inv0;
        float inv1 = gamma[o1] * rsqrtf(var[o1] + BN_EPS);
        float bi1  = beta[o1] - mean[o1] * inv1;
#pragma unroll
        for (int nt = 0; nt < 8; nt++) {
            int c = n0 + warp_n + nt * 8 + 2 * tg;
            float* a4 = acc[mt][nt];
            size_t b0 = (size_t)n * CIN * HW + (size_t)o0 * HW + c;
            size_t b1 = (size_t)n * CIN * HW + (size_t)o1 * HW + c;
            float2 x0 = *(const float2*)(x + b0);
            float2 x1 = *(const float2*)(x + b1);
            *(float2*)(out + b0) = make_float2(
                fmaxf(a4[0] * inv0 + bi0 + x0.x, 0.f),
                fmaxf(a4[1] * inv0 + bi0 + x0.y, 0.f));
            *(float2*)(out + b1) = make_float2(
                fmaxf(a4[2] * inv1 + bi1 + x1.x, 0.f),
                fmaxf(a4[3] * inv1 + bi1 + x1.y, 0.f));
        }
    }
}

// ---------------------------------------------------------------------------
extern "C" void kernel_launch(void* const* d_in, const int* in_sizes, int n_in,
                              void* d_out, int out_size) {
    const float* x       = (const float*)d_in[0];
    const float* conv1_w = (const float*)d_in[1];
    const float* gamma1  = (const float*)d_in[2];
    const float* beta1   = (const float*)d_in[3];
    const float* mean1   = (const float*)d_in[4];
    const float* var1    = (const float*)d_in[5];
    const float* qk_w    = (const float*)d_in[6];
    const float* v_w     = (const float*)d_in[7];
    const float* pos_h   = (const float*)d_in[8];
    const float* pos_w   = (const float*)d_in[9];
    const float* conv3_w = (const float*)d_in[10];
    const float* gamma3  = (const float*)d_in[11];
    const float* beta3   = (const float*)d_in[12];
    const float* mean3   = (const float*)d_in[13];
    const float* var3    = (const float*)d_in[14];
    float* out = (float*)d_out;

    cudaFuncSetAttribute(k_flash, cudaFuncAttributeMaxDynamicSharedMemorySize,
                         FLASH_SMEM);

    dim3 blk(256);
    k_gemm1<<<dim3(8, 4, NB), blk>>>(x, conv1_w, gamma1, beta1, mean1, var1);
    k_gemm2<<<dim3(8, 12, NB), blk>>>(qk_w, v_w, pos_h, pos_w);
    k_flash<<<dim3(HW / FX, 1, NB * NHEAD), blk, FLASH_SMEM>>>();
    k_gemm3<<<dim3(8, 16, NB), blk>>>(conv3_w, gamma3, beta3, mean3, var3, x, out);
}

// round 5
// speedup vs baseline: 2.7367x; 1.0529x over previous
#include <cuda_runtime.h>
#include <cuda_bf16.h>
#include <cstdint>
#include <cstddef>

// Problem constants
#define NB   16
#define CIN  2048
#define MID  512          // heads*dv = 4*128
#define HW   1024         // 32*32
#define DQK  128
#define NHEAD 4
#define ATT_SCALE 0.08838834764831845f   // 1/sqrt(128)
#define BN_EPS 1e-5f

// GEMM tile config: block 128x128, K-chunk 32, 8 warps of 32(M)x64(N)
#define LDA 36
#define LDB 136
#define ASZ (128 * LDA)                     // 4608 floats per A stage
#define BSZ (32 * LDB)                      // 4352 floats per B stage
#define GEMM_SMEM ((2 * ASZ + 2 * BSZ) * 4) // 71680 B

// Flash tile config
#define FX 64             // x rows per block
#define LDQ 132
#define Q_ELE (FX * LDQ)
#define S_OFF Q_ELE
#define B_OFF (2 * Q_ELE)
#define MB_OFF (B_OFF + 32 * LDB)
#define LB_OFF (MB_OFF + FX)
#define SC_OFF (LB_OFF + FX)
#define FLASH_SMEM ((SC_OFF + FX) * 4)     // ~85.8 KB

// Scratch (device globals — allocation-free kernel_launch)
__device__ float g_out1[(size_t)NB * MID * HW];           // 33.5 MB (tf32-rounded)
__device__ float g_qk  [(size_t)NB * 1024 * HW];          // 67 MB   (q' then k')
__device__ float g_v   [(size_t)NB * MID * HW];           // 33.5 MB
__device__ float g_attn[(size_t)NB * MID * HW];           // 33.5 MB (tf32-rounded)
__device__ float g_x   [(size_t)NB * CIN * HW];           // 134 MB  (tf32-rounded x)
__device__ float g_w1  [(size_t)MID * CIN];               // 4 MB
__device__ float g_wqkv[(size_t)1536 * MID];              // 3 MB (qk_w then v_w)
__device__ float g_w3  [(size_t)CIN * MID];               // 4 MB

// ---------------------------------------------------------------------------
__device__ __forceinline__ float f2tf(float f) {
    uint32_t u;
    asm("cvt.rna.tf32.f32 %0, %1;" : "=r"(u) : "f"(f));
    return __uint_as_float(u);
}

__device__ __forceinline__ void cp16(float* dst, const float* src) {
    uint32_t d = (uint32_t)__cvta_generic_to_shared(dst);
    asm volatile("cp.async.cg.shared.global [%0], [%1], 16;\n" :: "r"(d), "l"(src));
}
#define CP_COMMIT asm volatile("cp.async.commit_group;\n" ::: "memory")
#define CP_WAIT0  asm volatile("cp.async.wait_group 0;\n" ::: "memory")

// tf32 pre-round: dst[i] = round_tf32(src[i]), vectorized
__global__ __launch_bounds__(256) void k_round(const float4* __restrict__ src,
                                               float4* __restrict__ dst, int n4) {
    int i = blockIdx.x * blockDim.x + threadIdx.x;
    if (i < n4) {
        float4 v = src[i];
        dst[i] = make_float4(f2tf(v.x), f2tf(v.y), f2tf(v.z), f2tf(v.w));
    }
}

// ---- async tile loaders (data already tf32-rounded in gmem) ----
// A: [128 rows(M), 32 cols(K)] from row-major src (stride ld)
__device__ __forceinline__ void load_A_async(float* sA, const float* __restrict__ src,
                                             int ld, int tid) {
#pragma unroll
    for (int i = 0; i < 4; i++) {
        int g = tid + i * 256;
        int row = g >> 3, kq = (g & 7) * 4;
        cp16(sA + row * LDA + kq, src + (size_t)row * ld + kq);
    }
}
// B: [32 rows(K), 128 cols(N)] from row-major src (stride ld)
__device__ __forceinline__ void load_B_async(float* sB, const float* __restrict__ src,
                                             int ld, int tid) {
#pragma unroll
    for (int i = 0; i < 4; i++) {
        int g = tid + i * 256;
        int k = g >> 5, nq = (g & 31) * 4;
        cp16(sB + k * LDB + nq, src + (size_t)k * ld + nq);
    }
}

// ---- sync loaders with tf32 convert (flash kernel only) ----
__device__ __forceinline__ void load_B_direct(float* sB, const float* __restrict__ src,
                                              int ld, int tid) {
#pragma unroll
    for (int i = 0; i < 4; i++) {
        int g = tid + i * 256;
        int k = g >> 5, nq = (g & 31) * 4;
        float4 v = *(const float4*)(src + (size_t)k * ld + nq);
        float* p = sB + k * LDB + nq;
        p[0] = f2tf(v.x); p[1] = f2tf(v.y); p[2] = f2tf(v.z); p[3] = f2tf(v.w);
    }
}
__device__ __forceinline__ void load_B_trans(float* sB, const float* __restrict__ src,
                                             int ld, int tid) {
#pragma unroll
    for (int i = 0; i < 4; i++) {
        int g = tid + i * 256;
        int n = g >> 3, kq = (g & 7) * 4;
        float4 v = *(const float4*)(src + (size_t)n * ld + kq);
        sB[(kq + 0) * LDB + n] = f2tf(v.x);
        sB[(kq + 1) * LDB + n] = f2tf(v.y);
        sB[(kq + 2) * LDB + n] = f2tf(v.z);
        sB[(kq + 3) * LDB + n] = f2tf(v.w);
    }
}

// One K-chunk (32) of MMAs, warp tile 32(M) x 64(N): acc[2][8][4]
__device__ __forceinline__ void warp_mma(const float* sA, const float* sB,
                                         float acc[2][8][4],
                                         int warp_m, int warp_n, int lane) {
    int grp = lane >> 2, tg = lane & 3;
#pragma unroll
    for (int ks = 0; ks < 4; ks++) {
        int kk = ks * 8;
        uint32_t a[2][4];
#pragma unroll
        for (int mt = 0; mt < 2; mt++) {
            const float* base = sA + (warp_m + mt * 16 + grp) * LDA + kk + tg;
            a[mt][0] = __float_as_uint(base[0]);
            a[mt][1] = __float_as_uint(base[8 * LDA]);
            a[mt][2] = __float_as_uint(base[4]);
            a[mt][3] = __float_as_uint(base[8 * LDA + 4]);
        }
#pragma unroll
        for (int nt = 0; nt < 8; nt++) {
            const float* bb = sB + (kk + tg) * LDB + warp_n + nt * 8 + grp;
            uint32_t b0 = __float_as_uint(bb[0]);
            uint32_t b1 = __float_as_uint(bb[4 * LDB]);
#pragma unroll
            for (int mt = 0; mt < 2; mt++) {
                asm volatile(
                    "mma.sync.aligned.m16n8k8.row.col.f32.tf32.tf32.f32 "
                    "{%0,%1,%2,%3}, {%4,%5,%6,%7}, {%8,%9}, {%0,%1,%2,%3};\n"
                    : "+f"(acc[mt][nt][0]), "+f"(acc[mt][nt][1]),
                      "+f"(acc[mt][nt][2]), "+f"(acc[mt][nt][3])
                    : "r"(a[mt][0]), "r"(a[mt][1]), "r"(a[mt][2]), "r"(a[mt][3]),
                      "r"(b0), "r"(b1));
            }
        }
    }
}

// Flash variant: warp tile 32(M) x 32(N), A row stride LDQ: acc[2][4][4]
__device__ __forceinline__ void warp_mma_f(const float* A, const float* sB,
                                           float acc[2][4][4],
                                           int wm, int wn, int lane) {
    int grp = lane >> 2, tg = lane & 3;
#pragma unroll
    for (int ks = 0; ks < 4; ks++) {
        int kk = ks * 8;
        uint32_t a[2][4];
#pragma unroll
        for (int mt = 0; mt < 2; mt++) {
            const float* base = A + (wm + mt * 16 + grp) * LDQ + kk + tg;
            a[mt][0] = __float_as_uint(base[0]);
            a[mt][1] = __float_as_uint(base[8 * LDQ]);
            a[mt][2] = __float_as_uint(base[4]);
            a[mt][3] = __float_as_uint(base[8 * LDQ + 4]);
        }
#pragma unroll
        for (int nt = 0; nt < 4; nt++) {
            const float* bb = sB + (kk + tg) * LDB + wn + nt * 8 + grp;
            uint32_t b0 = __float_as_uint(bb[0]);
            uint32_t b1 = __float_as_uint(bb[4 * LDB]);
#pragma unroll
            for (int mt = 0; mt < 2; mt++) {
                asm volatile(
                    "mma.sync.aligned.m16n8k8.row.col.f32.tf32.tf32.f32 "
                    "{%0,%1,%2,%3}, {%4,%5,%6,%7}, {%8,%9}, {%0,%1,%2,%3};\n"
                    : "+f"(acc[mt][nt][0]), "+f"(acc[mt][nt][1]),
                      "+f"(acc[mt][nt][2]), "+f"(acc[mt][nt][3])
                    : "r"(a[mt][0]), "r"(a[mt][1]), "r"(a[mt][2]), "r"(a[mt][3]),
                      "r"(b0), "r"(b1));
            }
        }
    }
}

// ---------------------------------------------------------------------------
// GEMM mainloop (2-stage cp.async pipeline). Returns with acc filled.
// ---------------------------------------------------------------------------
__device__ __forceinline__ void gemm_mainloop(
    float* smp, const float* __restrict__ wp, int lda_g,
    const float* __restrict__ bp, int ldb_g, int nchunks,
    float acc[2][8][4], int warp_m, int warp_n, int lane, int tid) {
    float* sA0 = smp;
    float* sA1 = smp + ASZ;
    float* sB0 = smp + 2 * ASZ;
    float* sB1 = smp + 2 * ASZ + BSZ;
    load_A_async(sA0, wp, lda_g, tid);
    load_B_async(sB0, bp, ldb_g, tid);
    CP_COMMIT;
    for (int c = 0; c < nchunks; c++) {
        float* cA = (c & 1) ? sA1 : sA0;
        float* cB = (c & 1) ? sB1 : sB0;
        float* nA = (c & 1) ? sA0 : sA1;
        float* nB = (c & 1) ? sB0 : sB1;
        CP_WAIT0;
        __syncthreads();
        if (c + 1 < nchunks) {
            load_A_async(nA, wp + (c + 1) * 32, lda_g, tid);
            load_B_async(nB, bp + (size_t)(c + 1) * 32 * ldb_g, ldb_g, tid);
            CP_COMMIT;
        }
        warp_mma(cA, cB, acc, warp_m, warp_n, lane);
    }
}

// ---------------------------------------------------------------------------
// GEMM1: out1 = tf32(relu(BN(w1 @ x)))   M=512, K=2048, N=1024
// ---------------------------------------------------------------------------
__global__ __launch_bounds__(256, 2) void k_gemm1(
    const float* __restrict__ gamma, const float* __restrict__ beta,
    const float* __restrict__ mean, const float* __restrict__ var) {
    extern __shared__ float smp[];
    int n = blockIdx.z, m0 = blockIdx.y * 128, n0 = blockIdx.x * 128;
    int tid = threadIdx.x, lane = tid & 31, warp = tid >> 5;
    int warp_m = (warp & 3) * 32, warp_n = (warp >> 2) * 64;
    int grp = lane >> 2, tg = lane & 3;
    float acc[2][8][4] = {};
    gemm_mainloop(smp, g_w1 + (size_t)m0 * CIN, CIN,
                  g_x + (size_t)n * CIN * HW + n0, HW, CIN / 32,
                  acc, warp_m, warp_n, lane, tid);
    float* outb = g_out1 + (size_t)n * MID * HW;
#pragma unroll
    for (int mt = 0; mt < 2; mt++) {
        int o0 = m0 + warp_m + mt * 16 + grp, o1 = o0 + 8;
        float inv0 = gamma[o0] * rsqrtf(var[o0] + BN_EPS);
        float bi0  = beta[o0] - mean[o0] * inv0;
        float inv1 = gamma[o1] * rsqrtf(var[o1] + BN_EPS);
        float bi1  = beta[o1] - mean[o1] * inv1;
#pragma unroll
        for (int nt = 0; nt < 8; nt++) {
            int c = n0 + warp_n + nt * 8 + 2 * tg;
            float* a4 = acc[mt][nt];
            *(float2*)(outb + (size_t)o0 * HW + c) = make_float2(
                f2tf(fmaxf(a4[0] * inv0 + bi0, 0.f)),
                f2tf(fmaxf(a4[1] * inv0 + bi0, 0.f)));
            *(float2*)(outb + (size_t)o1 * HW + c) = make_float2(
                f2tf(fmaxf(a4[2] * inv1 + bi1, 0.f)),
                f2tf(fmaxf(a4[3] * inv1 + bi1, 0.f)));
        }
    }
}

// ---------------------------------------------------------------------------
// GEMM2: [q;k;v] projections   M=1536, K=512, N=1024
// ---------------------------------------------------------------------------
__global__ __launch_bounds__(256, 2) void k_gemm2(
    const float* __restrict__ pos_h, const float* __restrict__ pos_w) {
    extern __shared__ float smp[];
    int n = blockIdx.z, m0 = blockIdx.y * 128, n0 = blockIdx.x * 128;
    int tid = threadIdx.x, lane = tid & 31, warp = tid >> 5;
    int warp_m = (warp & 3) * 32, warp_n = (warp >> 2) * 64;
    int grp = lane >> 2, tg = lane & 3;
    float acc[2][8][4] = {};
    gemm_mainloop(smp, g_wqkv + (size_t)m0 * MID, MID,
                  g_out1 + (size_t)n * MID * HW + n0, HW, MID / 32,
                  acc, warp_m, warp_n, lane, tid);
#pragma unroll
    for (int mt = 0; mt < 2; mt++) {
        int o0 = m0 + warp_m + mt * 16 + grp;
#pragma unroll
        for (int half = 0; half < 2; half++) {
            int o = o0 + half * 8;
#pragma unroll
            for (int nt = 0; nt < 8; nt++) {
                int c = n0 + warp_n + nt * 8 + 2 * tg;
                float v0 = acc[mt][nt][half * 2 + 0];
                float v1 = acc[mt][nt][half * 2 + 1];
                if (o < 512) {                       // q' = q * scale
                    float* p = g_qk + (size_t)n * 1024 * HW + (size_t)o * HW + c;
                    *(float2*)p = make_float2(v0 * ATT_SCALE, v1 * ATT_SCALE);
                } else if (o < 1024) {               // k' = k + emb[y, d]
                    int d = (o - 512) & 127;
                    int hh = c >> 5, ww = c & 31;
                    float ph = pos_h[hh * DQK + d];
                    float e0 = ph + pos_w[ww * DQK + d];
                    float e1 = ph + pos_w[(ww + 1) * DQK + d];
                    float* p = g_qk + (size_t)n * 1024 * HW + (size_t)o * HW + c;
                    *(float2*)p = make_float2(v0 + e0, v1 + e1);
                } else {                             // v
                    float* p = g_v + (size_t)n * MID * HW + (size_t)(o - 1024) * HW + c;
                    *(float2*)p = make_float2(v0, v1);
                }
            }
        }
    }
}

// ---------------------------------------------------------------------------
// Fused flash attention (unchanged from round 3, + tf32 round on final store)
// ---------------------------------------------------------------------------
__global__ __launch_bounds__(256, 2) void k_flash() {
    extern __shared__ float sm[];
    float* Qs    = sm;
    float* Ss    = sm + S_OFF;
    float* sB    = sm + B_OFF;
    float* sm_m  = sm + MB_OFF;
    float* sm_l  = sm + LB_OFF;
    float* sm_sc = sm + SC_OFF;

    int z = blockIdx.z;
    int n = z >> 2, head = z & 3;
    int x0 = blockIdx.x * FX;
    int tid = threadIdx.x, lane = tid & 31, warp = tid >> 5;
    int wm = (warp & 1) * 32, wn = (warp >> 1) * 32;
    int grp = lane >> 2, tg = lane & 3;

    const float* qp = g_qk + (size_t)n * 1024 * HW + (size_t)head * DQK * HW;
    const float* kp = qp + (size_t)512 * HW;
    const float* vp = g_v + (size_t)n * MID * HW + (size_t)head * DQK * HW;

#pragma unroll
    for (int i = 0; i < 8; i++) {
        int g = tid + i * 256;
        int d = g >> 4, xq = (g & 15) * 4;
        float4 v = *(const float4*)(qp + (size_t)d * HW + x0 + xq);
        Qs[(xq + 0) * LDQ + d] = f2tf(v.x);
        Qs[(xq + 1) * LDQ + d] = f2tf(v.y);
        Qs[(xq + 2) * LDQ + d] = f2tf(v.z);
        Qs[(xq + 3) * LDQ + d] = f2tf(v.w);
    }
    if (tid < FX) { sm_m[tid] = -1e30f; sm_l[tid] = 0.f; }
    float acc_o[2][4][4] = {};
    float acc_s[2][4][4] = {};
    __syncthreads();

    for (int j = 0; j < 8; j++) {
        int y0 = j * 128;
        for (int c = 0; c < 4; c++) {
            __syncthreads();
            load_B_direct(sB, kp + (size_t)(c * 32) * HW + y0, HW, tid);
            __syncthreads();
            warp_mma_f(Qs + c * 32, sB, acc_s, wm, wn, lane);
        }
        __syncthreads();
#pragma unroll
        for (int mt = 0; mt < 2; mt++) {
            int r0 = wm + mt * 16 + grp, r1 = r0 + 8;
#pragma unroll
            for (int nt = 0; nt < 4; nt++) {
                int c = wn + nt * 8 + 2 * tg;
                Ss[r0 * LDQ + c]     = acc_s[mt][nt][0];
                Ss[r0 * LDQ + c + 1] = acc_s[mt][nt][1];
                Ss[r1 * LDQ + c]     = acc_s[mt][nt][2];
                Ss[r1 * LDQ + c + 1] = acc_s[mt][nt][3];
                acc_s[mt][nt][0] = acc_s[mt][nt][1] = 0.f;
                acc_s[mt][nt][2] = acc_s[mt][nt][3] = 0.f;
            }
        }
        __syncthreads();
        {
            int r = tid >> 2, q = tid & 3;
            float* row = Ss + r * LDQ;
            float mloc = -1e30f;
#pragma unroll
            for (int i = 0; i < 32; i++) mloc = fmaxf(mloc, row[q + 4 * i]);
            mloc = fmaxf(mloc, __shfl_xor_sync(0xffffffff, mloc, 1));
            mloc = fmaxf(mloc, __shfl_xor_sync(0xffffffff, mloc, 2));
            float m_old = sm_m[r];
            float m_new = fmaxf(m_old, mloc);
            float s = 0.f;
#pragma unroll
            for (int i = 0; i < 32; i++) {
                float p = __expf(row[q + 4 * i] - m_new);
                row[q + 4 * i] = f2tf(p);
                s += p;
            }
            s += __shfl_xor_sync(0xffffffff, s, 1);
            s += __shfl_xor_sync(0xffffffff, s, 2);
            if (q == 0) {
                sm_sc[r] = __expf(m_old - m_new);
                sm_m[r]  = m_new;
                sm_l[r]  = sm_l[r] * sm_sc[r] + s;
            }
        }
        __syncthreads();
#pragma unroll
        for (int mt = 0; mt < 2; mt++) {
            int r0 = wm + mt * 16 + grp;
            float s0 = sm_sc[r0], s1 = sm_sc[r0 + 8];
#pragma unroll
            for (int nt = 0; nt < 4; nt++) {
                acc_o[mt][nt][0] *= s0; acc_o[mt][nt][1] *= s0;
                acc_o[mt][nt][2] *= s1; acc_o[mt][nt][3] *= s1;
            }
        }
        for (int c = 0; c < 4; c++) {
            __syncthreads();
            load_B_trans(sB, vp + y0 + c * 32, HW, tid);
            __syncthreads();
            warp_mma_f(Ss + c * 32, sB, acc_o, wm, wn, lane);
        }
    }

    __syncthreads();
#pragma unroll
    for (int mt = 0; mt < 2; mt++) {
        int r0 = wm + mt * 16 + grp, r1 = r0 + 8;
        float l0 = 1.f / sm_l[r0], l1 = 1.f / sm_l[r1];
#pragma unroll
        for (int nt = 0; nt < 4; nt++) {
            int c = wn + nt * 8 + 2 * tg;
            Ss[r0 * LDQ + c]     = fmaxf(acc_o[mt][nt][0] * l0, 0.f);
            Ss[r0 * LDQ + c + 1] = fmaxf(acc_o[mt][nt][1] * l0, 0.f);
            Ss[r1 * LDQ + c]     = fmaxf(acc_o[mt][nt][2] * l1, 0.f);
            Ss[r1 * LDQ + c + 1] = fmaxf(acc_o[mt][nt][3] * l1, 0.f);
        }
    }
    __syncthreads();
    float* op = g_attn + (size_t)n * MID * HW + (size_t)head * DQK * HW;
#pragma unroll
    for (int i = 0; i < 32; i++) {
        int g = tid + i * 256;
        int d = g >> 6, xo = g & 63;
        op[(size_t)d * HW + x0 + xo] = f2tf(Ss[xo * LDQ + d]);
    }
}

// ---------------------------------------------------------------------------
// GEMM3: out = relu(BN(w3 @ attn) + x)   M=2048, K=512, N=1024
// ---------------------------------------------------------------------------
__global__ __launch_bounds__(256, 2) void k_gemm3(
    const float* __restrict__ gamma, const float* __restrict__ beta,
    const float* __restrict__ mean, const float* __restrict__ var,
    const float* __restrict__ x, float* __restrict__ out) {
    extern __shared__ float smp[];
    int n = blockIdx.z, m0 = blockIdx.y * 128, n0 = blockIdx.x * 128;
    int tid = threadIdx.x, lane = tid & 31, warp = tid >> 5;
    int warp_m = (warp & 3) * 32, warp_n = (warp >> 2) * 64;
    int grp = lane >> 2, tg = lane & 3;
    float acc[2][8][4] = {};
    gemm_mainloop(smp, g_w3 + (size_t)m0 * MID, MID,
                  g_attn + (size_t)n * MID * HW + n0, HW, MID / 32,
                  acc, warp_m, warp_n, lane, tid);
#pragma unroll
    for (int mt = 0; mt < 2; mt++) {
        int o0 = m0 + warp_m + mt * 16 + grp, o1 = o0 + 8;
        float inv0 = gamma[o0] * rsqrtf(var[o0] + BN_EPS);
        float bi0  = beta[o0] - mean[o0] * inv0;
        float inv1 = gamma[o1] * rsqrtf(var[o1] + BN_EPS);
        float bi1  = beta[o1] - mean[o1] * inv1;
#pragma unroll
        for (int nt = 0; nt < 8; nt++) {
            int c = n0 + warp_n + nt * 8 + 2 * tg;
            float* a4 = acc[mt][nt];
            size_t b0 = (size_t)n * CIN * HW + (size_t)o0 * HW + c;
            size_t b1 = (size_t)n * CIN * HW + (size_t)o1 * HW + c;
            float2 x0 = *(const float2*)(x + b0);
            float2 x1 = *(const float2*)(x + b1);
            *(float2*)(out + b0) = make_float2(
                fmaxf(a4[0] * inv0 + bi0 + x0.x, 0.f),
                fmaxf(a4[1] * inv0 + bi0 + x0.y, 0.f));
            *(float2*)(out + b1) = make_float2(
                fmaxf(a4[2] * inv1 + bi1 + x1.x, 0.f),
                fmaxf(a4[3] * inv1 + bi1 + x1.y, 0.f));
        }
    }
}

// ---------------------------------------------------------------------------
extern "C" void kernel_launch(void* const* d_in, const int* in_sizes, int n_in,
                              void* d_out, int out_size) {
    const float* x       = (const float*)d_in[0];
    const float* conv1_w = (const float*)d_in[1];
    const float* gamma1  = (const float*)d_in[2];
    const float* beta1   = (const float*)d_in[3];
    const float* mean1   = (const float*)d_in[4];
    const float* var1    = (const float*)d_in[5];
    const float* qk_w    = (const float*)d_in[6];
    const float* v_w     = (const float*)d_in[7];
    const float* pos_h   = (const float*)d_in[8];
    const float* pos_w   = (const float*)d_in[9];
    const float* conv3_w = (const float*)d_in[10];
    const float* gamma3  = (const float*)d_in[11];
    const float* beta3   = (const float*)d_in[12];
    const float* mean3   = (const float*)d_in[13];
    const float* var3    = (const float*)d_in[14];
    float* out = (float*)d_out;

    static bool attr_done = false;
    if (!attr_done) {
        cudaFuncSetAttribute(k_flash, cudaFuncAttributeMaxDynamicSharedMemorySize,
                             FLASH_SMEM);
        cudaFuncSetAttribute(k_gemm1, cudaFuncAttributeMaxDynamicSharedMemorySize,
                             GEMM_SMEM);
        cudaFuncSetAttribute(k_gemm2, cudaFuncAttributeMaxDynamicSharedMemorySize,
                             GEMM_SMEM);
        cudaFuncSetAttribute(k_gemm3, cudaFuncAttributeMaxDynamicSharedMemorySize,
                             GEMM_SMEM);
        attr_done = true;
    }

    // resolve device-global scratch addresses (host-side, not captured ops)
    float *p_x, *p_w1, *p_wqkv, *p_w3;
    cudaGetSymbolAddress((void**)&p_x, g_x);
    cudaGetSymbolAddress((void**)&p_w1, g_w1);
    cudaGetSymbolAddress((void**)&p_wqkv, g_wqkv);
    cudaGetSymbolAddress((void**)&p_w3, g_w3);

    dim3 blk(256);
    // tf32 pre-round of all GEMM operands
    {
        int n4 = NB * CIN * HW / 4;
        k_round<<<(n4 + 255) / 256, blk>>>((const float4*)x, (float4*)p_x, n4);
        n4 = MID * CIN / 4;
        k_round<<<(n4 + 255) / 256, blk>>>((const float4*)conv1_w, (float4*)p_w1, n4);
        n4 = 1024 * MID / 4;
        k_round<<<(n4 + 255) / 256, blk>>>((const float4*)qk_w, (float4*)p_wqkv, n4);
        n4 = 512 * MID / 4;
        k_round<<<(n4 + 255) / 256, blk>>>((const float4*)v_w,
                                           (float4*)(p_wqkv + (size_t)1024 * MID), n4);
        n4 = CIN * MID / 4;
        k_round<<<(n4 + 255) / 256, blk>>>((const float4*)conv3_w, (float4*)p_w3, n4);
    }

    k_gemm1<<<dim3(8, 4, NB), blk, GEMM_SMEM>>>(gamma1, beta1, mean1, var1);
    k_gemm2<<<dim3(8, 12, NB), blk, GEMM_SMEM>>>(pos_h, pos_w);
    k_flash<<<dim3(HW / FX, 1, NB * NHEAD), blk, FLASH_SMEM>>>();
    k_gemm3<<<dim3(8, 16, NB), blk, GEMM_SMEM>>>(gamma3, beta3, mean3, var3, x, out);
}

// round 7
// speedup vs baseline: 3.1590x; 1.1543x over previous
#include <cuda_runtime.h>
#include <cuda_bf16.h>
#include <cstdint>
#include <cstddef>

// Problem constants
#define NB   16
#define CIN  2048
#define MID  512
#define HW   1024
#define DQK  128
#define NHEAD 4
#define ATT_SCALE 0.08838834764831845f
#define BN_EPS 1e-5f

// GEMM tile config: block 128x128, K-chunk 32, 8 warps of 32(M)x64(N)
#define LDB 136
#define ASZ 4096                       // A stage floats (fragment-packed, no pad)
#define BSZ (32 * LDB)                 // 4352 floats
#define GEMM_SMEM ((3 * ASZ + 3 * BSZ) * 4)   // 101376 B

// Flash tile config: x-tile 128, 512 threads (16 warps of 32x32)
#define FLDQ 132
#define F_S  (128 * FLDQ)              // 16896
#define F_B  (2 * F_S)                 // 33792
#define F_M  (F_B + 3 * BSZ)           // 46848
#define F_L  (F_M + 128)
#define F_SC (F_L + 128)
#define FLASH_SMEM ((F_SC + 128) * 4)  // 188928 B

// Scratch (device globals — allocation-free kernel_launch)
__device__ float g_x   [(size_t)NB * CIN * HW];   // tf32-rounded x [n][ch][pos]
__device__ float g_out1[(size_t)NB * MID * HW];   // [n][ch][pos], tf32
__device__ float g_qk  [(size_t)NB * 1024 * HW];  // q'[d][x] then k'[d][y], tf32
__device__ float g_vT  [(size_t)NB * HW * MID];   // v [n][y][ch], tf32
__device__ float g_attn[(size_t)NB * MID * HW];   // [n][ch][pos], tf32
__device__ float g_w1  [(size_t)MID * CIN];       // fragment-packed tiles
__device__ float g_wqkv[(size_t)1536 * MID];      // fragment-packed tiles
__device__ float g_w3  [(size_t)CIN * MID];       // fragment-packed tiles

// ---------------------------------------------------------------------------
__device__ __forceinline__ float f2tf(float f) {
    uint32_t u;
    asm("cvt.rna.tf32.f32 %0, %1;" : "=r"(u) : "f"(f));
    return __uint_as_float(u);
}

__device__ __forceinline__ void cp16(float* dst, const float* src) {
    uint32_t d = (uint32_t)__cvta_generic_to_shared(dst);
    asm volatile("cp.async.cg.shared.global [%0], [%1], 16;\n" :: "r"(d), "l"(src));
}
#define CP_COMMIT asm volatile("cp.async.commit_group;\n" ::: "memory")
#define CP_WAIT0  asm volatile("cp.async.wait_group 0;\n" ::: "memory")
#define CP_WAIT1  asm volatile("cp.async.wait_group 1;\n" ::: "memory")

// ---------------------------------------------------------------------------
// elementwise tf32 round (x)
// ---------------------------------------------------------------------------
__global__ __launch_bounds__(256) void k_round(const float4* __restrict__ src,
                                               float4* __restrict__ dst, int n4) {
    int i = blockIdx.x * blockDim.x + threadIdx.x;
    if (i < n4) {
        float4 v = src[i];
        dst[i] = make_float4(f2tf(v.x), f2tf(v.y), f2tf(v.z), f2tf(v.w));
    }
}

// ---------------------------------------------------------------------------
// Weight repack: W[M][K] row-major -> fragment-ordered tiles
// [mtile][ktile][blk=((wm*2+mt)*4+ks)][lane][4] ; a0,a1,a2,a3 per lane.
// ---------------------------------------------------------------------------
__global__ __launch_bounds__(256) void k_repack(const float* __restrict__ src,
                                                float* __restrict__ dst,
                                                int M, int K) {
    int e = blockIdx.x * 256 + threadIdx.x;
    if (e >= M * K) return;
    int ktiles = K >> 5;
    int tile = e >> 12, within = e & 4095;
    int mtile = tile / ktiles, ktile = tile - mtile * ktiles;
    int blk = within >> 7, lanei = within & 127;
    int lane = lanei >> 2, i = lanei & 3;
    int wm = blk >> 3, mt = (blk >> 2) & 1, ks = blk & 3;
    int row = (mtile << 7) + (wm << 5) + (mt << 4) + (lane >> 2) + ((i & 1) << 3);
    int col = (ktile << 5) + (ks << 3) + (lane & 3) + ((i >> 1) << 2);
    dst[e] = f2tf(src[(size_t)row * K + col]);
}

// ---------------------------------------------------------------------------
// MMA helpers
// ---------------------------------------------------------------------------
// packed-A variant, warp tile 32(M) x 64(N): acc[2][8][4]
__device__ __forceinline__ void warp_mma_p(const float* sA, const float* sB,
                                           float acc[2][8][4],
                                           int wm, int warp_n, int lane) {
    int grp = lane >> 2, tg = lane & 3;
#pragma unroll
    for (int ks = 0; ks < 4; ks++) {
        int kk = ks * 8;
        float4 af[2];
#pragma unroll
        for (int mt = 0; mt < 2; mt++)
            af[mt] = *(const float4*)(sA + (((wm * 2 + mt) * 4 + ks) << 7) + (lane << 2));
#pragma unroll
        for (int nt = 0; nt < 8; nt++) {
            const float* bb = sB + (kk + tg) * LDB + warp_n + nt * 8 + grp;
            uint32_t b0 = __float_as_uint(bb[0]);
            uint32_t b1 = __float_as_uint(bb[4 * LDB]);
#pragma unroll
            for (int mt = 0; mt < 2; mt++) {
                asm volatile(
                    "mma.sync.aligned.m16n8k8.row.col.f32.tf32.tf32.f32 "
                    "{%0,%1,%2,%3}, {%4,%5,%6,%7}, {%8,%9}, {%0,%1,%2,%3};\n"
                    : "+f"(acc[mt][nt][0]), "+f"(acc[mt][nt][1]),
                      "+f"(acc[mt][nt][2]), "+f"(acc[mt][nt][3])
                    : "r"(__float_as_uint(af[mt].x)), "r"(__float_as_uint(af[mt].y)),
                      "r"(__float_as_uint(af[mt].z)), "r"(__float_as_uint(af[mt].w)),
                      "r"(b0), "r"(b1));
            }
        }
    }
}

// flash variant: A row-major stride FLDQ, warp tile 32(M) x 32(N): acc[2][4][4]
__device__ __forceinline__ void warp_mma_f(const float* A, const float* sB,
                                           float acc[2][4][4],
                                           int wm, int wn, int lane) {
    int grp = lane >> 2, tg = lane & 3;
#pragma unroll
    for (int ks = 0; ks < 4; ks++) {
        int kk = ks * 8;
        uint32_t a[2][4];
#pragma unroll
        for (int mt = 0; mt < 2; mt++) {
            const float* base = A + (wm + mt * 16 + grp) * FLDQ + kk + tg;
            a[mt][0] = __float_as_uint(base[0]);
            a[mt][1] = __float_as_uint(base[8 * FLDQ]);
            a[mt][2] = __float_as_uint(base[4]);
            a[mt][3] = __float_as_uint(base[8 * FLDQ + 4]);
        }
#pragma unroll
        for (int nt = 0; nt < 4; nt++) {
            const float* bb = sB + (kk + tg) * LDB + wn + nt * 8 + grp;
            uint32_t b0 = __float_as_uint(bb[0]);
            uint32_t b1 = __float_as_uint(bb[4 * LDB]);
#pragma unroll
            for (int mt = 0; mt < 2; mt++) {
                asm volatile(
                    "mma.sync.aligned.m16n8k8.row.col.f32.tf32.tf32.f32 "
                    "{%0,%1,%2,%3}, {%4,%5,%6,%7}, {%8,%9}, {%0,%1,%2,%3};\n"
                    : "+f"(acc[mt][nt][0]), "+f"(acc[mt][nt][1]),
                      "+f"(acc[mt][nt][2]), "+f"(acc[mt][nt][3])
                    : "r"(a[mt][0]), "r"(a[mt][1]), "r"(a[mt][2]), "r"(a[mt][3]),
                      "r"(b0), "r"(b1));
            }
        }
    }
}

// ---------------------------------------------------------------------------
// GEMM mainloop: 3-stage cp.async pipeline (wait_group 1, 1 sync/chunk)
// ---------------------------------------------------------------------------
__device__ __forceinline__ void gemm_mainloop3(
    float* smp, const float* __restrict__ Aw,
    const float* __restrict__ Bp, int ldb, int nchunks,
    float acc[2][8][4], int wm, int warp_n, int lane, int tid) {
    float* sA = smp;
    float* sB = smp + 3 * ASZ;
#pragma unroll
    for (int s = 0; s < 2; s++) {
        const float* a = Aw + s * ASZ;
#pragma unroll
        for (int i = 0; i < 4; i++)
            cp16(sA + s * ASZ + tid * 4 + i * 1024, a + tid * 4 + i * 1024);
#pragma unroll
        for (int i = 0; i < 4; i++) {
            int g = tid + i * 256, k = g >> 5, nq = (g & 31) * 4;
            cp16(sB + s * BSZ + k * LDB + nq, Bp + (size_t)(s * 32 + k) * ldb + nq);
        }
        CP_COMMIT;
    }
    for (int c = 0; c < nchunks; c++) {
        if (c == nchunks - 1) { CP_WAIT0; } else { CP_WAIT1; }
        __syncthreads();
        if (c + 2 < nchunks) {
            int s = (c + 2) % 3;
            const float* a = Aw + (size_t)(c + 2) * ASZ;
#pragma unroll
            for (int i = 0; i < 4; i++)
                cp16(sA + s * ASZ + tid * 4 + i * 1024, a + tid * 4 + i * 1024);
#pragma unroll
            for (int i = 0; i < 4; i++) {
                int g = tid + i * 256, k = g >> 5, nq = (g & 31) * 4;
                cp16(sB + s * BSZ + k * LDB + nq,
                     Bp + (size_t)((c + 2) * 32 + k) * ldb + nq);
            }
            CP_COMMIT;
        }
        warp_mma_p(sA + (c % 3) * ASZ, sB + (c % 3) * BSZ, acc, wm, warp_n, lane);
    }
}

// ---------------------------------------------------------------------------
// GEMM1: out1 = tf32(relu(BN(w1 @ x)))   M=512, K=2048, N=1024
// ---------------------------------------------------------------------------
__global__ __launch_bounds__(256, 2) void k_gemm1(
    const float* __restrict__ gamma, const float* __restrict__ beta,
    const float* __restrict__ mean, const float* __restrict__ var) {
    extern __shared__ float smp[];
    int n = blockIdx.z, m0 = blockIdx.y * 128, n0 = blockIdx.x * 128;
    int tid = threadIdx.x, lane = tid & 31, warp = tid >> 5;
    int wm = warp & 3, warp_n = (warp >> 2) * 64;
    int grp = lane >> 2, tg = lane & 3;
    float acc[2][8][4] = {};
    gemm_mainloop3(smp, g_w1 + (size_t)(m0 >> 7) * 64 * ASZ,
                   g_x + (size_t)n * CIN * HW + n0, HW, CIN / 32,
                   acc, wm, warp_n, lane, tid);
    float* outb = g_out1 + (size_t)n * MID * HW;
#pragma unroll
    for (int mt = 0; mt < 2; mt++) {
        int o0 = m0 + wm * 32 + mt * 16 + grp, o1 = o0 + 8;
        float inv0 = gamma[o0] * rsqrtf(var[o0] + BN_EPS);
        float bi0  = beta[o0] - mean[o0] * inv0;
        float inv1 = gamma[o1] * rsqrtf(var[o1] + BN_EPS);
        float bi1  = beta[o1] - mean[o1] * inv1;
#pragma unroll
        for (int nt = 0; nt < 8; nt++) {
            int c = n0 + warp_n + nt * 8 + 2 * tg;
            float* a4 = acc[mt][nt];
            *(float2*)(outb + (size_t)o0 * HW + c) = make_float2(
                f2tf(fmaxf(a4[0] * inv0 + bi0, 0.f)),
                f2tf(fmaxf(a4[1] * inv0 + bi0, 0.f)));
            *(float2*)(outb + (size_t)o1 * HW + c) = make_float2(
                f2tf(fmaxf(a4[2] * inv1 + bi1, 0.f)),
                f2tf(fmaxf(a4[3] * inv1 + bi1, 0.f)));
        }
    }
}

// ---------------------------------------------------------------------------
// GEMM2: [q';k';v] projections   M=1536, K=512, N=1024
// q'/k' -> g_qk (tf32-rounded); v -> g_vT [y][ch] (tf32-rounded)
// ---------------------------------------------------------------------------
__global__ __launch_bounds__(256, 2) void k_gemm2(
    const float* __restrict__ pos_h, const float* __restrict__ pos_w) {
    extern __shared__ float smp[];
    int n = blockIdx.z, m0 = blockIdx.y * 128, n0 = blockIdx.x * 128;
    int tid = threadIdx.x, lane = tid & 31, warp = tid >> 5;
    int wm = warp & 3, warp_n = (warp >> 2) * 64;
    int grp = lane >> 2, tg = lane & 3;
    float acc[2][8][4] = {};
    gemm_mainloop3(smp, g_wqkv + (size_t)(m0 >> 7) * 16 * ASZ,
                   g_out1 + (size_t)n * MID * HW + n0, HW, MID / 32,
                   acc, wm, warp_n, lane, tid);
#pragma unroll
    for (int mt = 0; mt < 2; mt++) {
        int o0 = m0 + wm * 32 + mt * 16 + grp;
#pragma unroll
        for (int half = 0; half < 2; half++) {
            int o = o0 + half * 8;
#pragma unroll
            for (int nt = 0; nt < 8; nt++) {
                int c = n0 + warp_n + nt * 8 + 2 * tg;
                float v0 = acc[mt][nt][half * 2 + 0];
                float v1 = acc[mt][nt][half * 2 + 1];
                if (o < 512) {                       // q' = tf32(q * scale)
                    float* p = g_qk + (size_t)n * 1024 * HW + (size_t)o * HW + c;
                    *(float2*)p = make_float2(f2tf(v0 * ATT_SCALE), f2tf(v1 * ATT_SCALE));
                } else if (o < 1024) {               // k' = tf32(k + emb)
                    int d = (o - 512) & 127;
                    int hh = c >> 5, ww = c & 31;
                    float ph = pos_h[hh * DQK + d];
                    float e0 = ph + pos_w[ww * DQK + d];
                    float e1 = ph + pos_w[(ww + 1) * DQK + d];
                    float* p = g_qk + (size_t)n * 1024 * HW + (size_t)o * HW + c;
                    *(float2*)p = make_float2(f2tf(v0 + e0), f2tf(v1 + e1));
                } else {                             // v -> transposed [y][ch]
                    int d = o - 1024;
                    g_vT[((size_t)n * HW + c)     * MID + d] = f2tf(v0);
                    g_vT[((size_t)n * HW + c + 1) * MID + d] = f2tf(v1);
                }
            }
        }
    }
}

// ---------------------------------------------------------------------------
// Flash attention: x-tile 128, 512 threads, 3-buffer cp.async K/V ring.
// ---------------------------------------------------------------------------
__global__ __launch_bounds__(512) void k_flash() {
    extern __shared__ float sm[];
    float* Qs    = sm;
    float* Ss    = sm + F_S;
    float* sBr   = sm + F_B;
    float* sm_m  = sm + F_M;
    float* sm_l  = sm + F_L;
    float* sm_sc = sm + F_SC;

    int z = blockIdx.z, n = z >> 2, head = z & 3;
    int x0 = blockIdx.x * 128;
    int tid = threadIdx.x, lane = tid & 31, warp = tid >> 5;
    int wm = (warp & 3) * 32, wn = (warp >> 2) * 32;
    int grp = lane >> 2, tg = lane & 3;

    const float* qp = g_qk + ((size_t)n * 1024 + head * DQK) * HW;  // [128 d][1024 x]
    const float* kp = qp + (size_t)512 * HW;                        // [128 d][1024 y]
    const float* vp = g_vT + (size_t)n * HW * MID + head * DQK;     // row y, stride MID

    auto load_chunk = [&](int t) {
        float* buf = sBr + (t % 3) * BSZ;
        int j = t >> 3, ph = t & 7;
        const float* src;
        int ld;
        if (ph < 4) { src = kp + ((size_t)ph * 32) * HW + j * 128; ld = HW; }
        else        { src = vp + ((size_t)(j * 128 + (ph - 4) * 32)) * MID; ld = MID; }
#pragma unroll
        for (int i = 0; i < 2; i++) {
            int g = tid + i * 512, k = g >> 5, nq = (g & 31) * 4;
            cp16(buf + k * LDB + nq, src + (size_t)k * ld + nq);
        }
    };

    load_chunk(0); CP_COMMIT;
    load_chunk(1); CP_COMMIT;

    // Q tile [128 x][128 d], transposed from [d][x] (already tf32)
#pragma unroll
    for (int i = 0; i < 8; i++) {
        int g = tid + i * 512;               // 4096 float4s
        int d = g >> 5, xq = (g & 31) * 4;
        float4 v = *(const float4*)(qp + (size_t)d * HW + x0 + xq);
        Qs[(xq + 0) * FLDQ + d] = v.x;
        Qs[(xq + 1) * FLDQ + d] = v.y;
        Qs[(xq + 2) * FLDQ + d] = v.z;
        Qs[(xq + 3) * FLDQ + d] = v.w;
    }
    if (tid < 128) { sm_m[tid] = -1e30f; sm_l[tid] = 0.f; }
    float acc_o[2][4][4] = {};
    float acc_s[2][4][4] = {};
    __syncthreads();

    for (int j = 0; j < 8; j++) {
        // ---- S = Q @ K'^T : chunks t = j*8 + 0..3 ----
        for (int c = 0; c < 4; c++) {
            int t = j * 8 + c;
            if (t == 63) { CP_WAIT0; } else { CP_WAIT1; }
            __syncthreads();
            if (t + 2 < 64) { load_chunk(t + 2); CP_COMMIT; }
            warp_mma_f(Qs + c * 32, sBr + (t % 3) * BSZ, acc_s, wm, wn, lane);
        }
        __syncthreads();
        // ---- write S tile, zero acc_s ----
#pragma unroll
        for (int mt = 0; mt < 2; mt++) {
            int r0 = wm + mt * 16 + grp, r1 = r0 + 8;
#pragma unroll
            for (int nt = 0; nt < 4; nt++) {
                int c = wn + nt * 8 + 2 * tg;
                Ss[r0 * FLDQ + c]     = acc_s[mt][nt][0];
                Ss[r0 * FLDQ + c + 1] = acc_s[mt][nt][1];
                Ss[r1 * FLDQ + c]     = acc_s[mt][nt][2];
                Ss[r1 * FLDQ + c + 1] = acc_s[mt][nt][3];
                acc_s[mt][nt][0] = acc_s[mt][nt][1] = 0.f;
                acc_s[mt][nt][2] = acc_s[mt][nt][3] = 0.f;
            }
        }
        __syncthreads();
        // ---- online softmax: 4 threads/row ----
        {
            int r = tid >> 2, q = tid & 3;
            float* row = Ss + r * FLDQ;
            float mloc = -1e30f;
#pragma unroll
            for (int i = 0; i < 32; i++) mloc = fmaxf(mloc, row[q + 4 * i]);
            mloc = fmaxf(mloc, __shfl_xor_sync(0xffffffff, mloc, 1));
            mloc = fmaxf(mloc, __shfl_xor_sync(0xffffffff, mloc, 2));
            float m_old = sm_m[r];
            float m_new = fmaxf(m_old, mloc);
            float s = 0.f;
#pragma unroll
            for (int i = 0; i < 32; i++) {
                float p = __expf(row[q + 4 * i] - m_new);
                row[q + 4 * i] = f2tf(p);
                s += p;
            }
            s += __shfl_xor_sync(0xffffffff, s, 1);
            s += __shfl_xor_sync(0xffffffff, s, 2);
            if (q == 0) {
                sm_sc[r] = __expf(m_old - m_new);
                sm_m[r]  = m_new;
                sm_l[r]  = sm_l[r] * sm_sc[r] + s;
            }
        }
        __syncthreads();
        // ---- rescale O accumulator ----
#pragma unroll
        for (int mt = 0; mt < 2; mt++) {
            int r0 = wm + mt * 16 + grp;
            float s0 = sm_sc[r0], s1 = sm_sc[r0 + 8];
#pragma unroll
            for (int nt = 0; nt < 4; nt++) {
                acc_o[mt][nt][0] *= s0; acc_o[mt][nt][1] *= s0;
                acc_o[mt][nt][2] *= s1; acc_o[mt][nt][3] *= s1;
            }
        }
        // ---- O += P @ V : chunks t = j*8 + 4..7 ----
        for (int c = 0; c < 4; c++) {
            int t = j * 8 + 4 + c;
            if (t == 63) { CP_WAIT0; } else { CP_WAIT1; }
            __syncthreads();
            if (t + 2 < 64) { load_chunk(t + 2); CP_COMMIT; }
            warp_mma_f(Ss + c * 32, sBr + (t % 3) * BSZ, acc_o, wm, wn, lane);
        }
    }

    // ---- epilogue: O /= l, relu, transpose via Ss, coalesced tf32 store ----
    __syncthreads();
#pragma unroll
    for (int mt = 0; mt < 2; mt++) {
        int r0 = wm + mt * 16 + grp, r1 = r0 + 8;
        float l0 = 1.f / sm_l[r0], l1 = 1.f / sm_l[r1];
#pragma unroll
        for (int nt = 0; nt < 4; nt++) {
            int c = wn + nt * 8 + 2 * tg;
            Ss[r0 * FLDQ + c]     = fmaxf(acc_o[mt][nt][0] * l0, 0.f);
            Ss[r0 * FLDQ + c + 1] = fmaxf(acc_o[mt][nt][1] * l0, 0.f);
            Ss[r1 * FLDQ + c]     = fmaxf(acc_o[mt][nt][2] * l1, 0.f);
            Ss[r1 * FLDQ + c + 1] = fmaxf(acc_o[mt][nt][3] * l1, 0.f);
        }
    }
    __syncthreads();
    float* op = g_attn + ((size_t)n * MID + head * DQK) * HW;   // rows d, cols x
#pragma unroll
    for (int i = 0; i < 32; i++) {
        int g = tid + i * 512;               // 16384 = 128 d * 128 x
        int d = g >> 7, xo = g & 127;
        op[(size_t)d * HW + x0 + xo] = f2tf(Ss[xo * FLDQ + d]);
    }
}

// ---------------------------------------------------------------------------
// GEMM3: out = relu(BN(w3 @ attn) + x)   M=2048, K=512, N=1024
// ---------------------------------------------------------------------------
__global__ __launch_bounds__(256, 2) void k_gemm3(
    const float* __restrict__ gamma, const float* __restrict__ beta,
    const float* __restrict__ mean, const float* __restrict__ var,
    const float* __restrict__ x, float* __restrict__ out) {
    extern __shared__ float smp[];
    int n = blockIdx.z, m0 = blockIdx.y * 128, n0 = blockIdx.x * 128;
    int tid = threadIdx.x, lane = tid & 31, warp = tid >> 5;
    int wm = warp & 3, warp_n = (warp >> 2) * 64;
    int grp = lane >> 2, tg = lane & 3;
    float acc[2][8][4] = {};
    gemm_mainloop3(smp, g_w3 + (size_t)(m0 >> 7) * 16 * ASZ,
                   g_attn + (size_t)n * MID * HW + n0, HW, MID / 32,
                   acc, wm, warp_n, lane, tid);
#pragma unroll
    for (int mt = 0; mt < 2; mt++) {
        int o0 = m0 + wm * 32 + mt * 16 + grp, o1 = o0 + 8;
        float inv0 = gamma[o0] * rsqrtf(var[o0] + BN_EPS);
        float bi0  = beta[o0] - mean[o0] * inv0;
        float inv1 = gamma[o1] * rsqrtf(var[o1] + BN_EPS);
        float bi1  = beta[o1] - mean[o1] * inv1;
#pragma unroll
        for (int nt = 0; nt < 8; nt++) {
            int c = n0 + warp_n + nt * 8 + 2 * tg;
            float* a4 = acc[mt][nt];
            size_t b0 = (size_t)n * CIN * HW + (size_t)o0 * HW + c;
            size_t b1 = (size_t)n * CIN * HW + (size_t)o1 * HW + c;
            float2 x0 = *(const float2*)(x + b0);
            float2 x1 = *(const float2*)(x + b1);
            *(float2*)(out + b0) = make_float2(
                fmaxf(a4[0] * inv0 + bi0 + x0.x, 0.f),
                fmaxf(a4[1] * inv0 + bi0 + x0.y, 0.f));
            *(float2*)(out + b1) = make_float2(
                fmaxf(a4[2] * inv1 + bi1 + x1.x, 0.f),
                fmaxf(a4[3] * inv1 + bi1 + x1.y, 0.f));
        }
    }
}

// ---------------------------------------------------------------------------
extern "C" void kernel_launch(void* const* d_in, const int* in_sizes, int n_in,
                              void* d_out, int out_size) {
    const float* x       = (const float*)d_in[0];
    const float* conv1_w = (const float*)d_in[1];
    const float* gamma1  = (const float*)d_in[2];
    const float* beta1   = (const float*)d_in[3];
    const float* mean1   = (const float*)d_in[4];
    const float* var1    = (const float*)d_in[5];
    const float* qk_w    = (const float*)d_in[6];
    const float* v_w     = (const float*)d_in[7];
    const float* pos_h   = (const float*)d_in[8];
    const float* pos_w   = (const float*)d_in[9];
    const float* conv3_w = (const float*)d_in[10];
    const float* gamma3  = (const float*)d_in[11];
    const float* beta3   = (const float*)d_in[12];
    const float* mean3   = (const float*)d_in[13];
    const float* var3    = (const float*)d_in[14];
    float* out = (float*)d_out;

    cudaFuncSetAttribute(k_flash, cudaFuncAttributeMaxDynamicSharedMemorySize,
                         FLASH_SMEM);
    cudaFuncSetAttribute(k_gemm1, cudaFuncAttributeMaxDynamicSharedMemorySize,
                         GEMM_SMEM);
    cudaFuncSetAttribute(k_gemm2, cudaFuncAttributeMaxDynamicSharedMemorySize,
                         GEMM_SMEM);
    cudaFuncSetAttribute(k_gemm3, cudaFuncAttributeMaxDynamicSharedMemorySize,
                         GEMM_SMEM);

    float *p_x, *p_w1, *p_wqkv, *p_w3;
    cudaGetSymbolAddress((void**)&p_x, g_x);
    cudaGetSymbolAddress((void**)&p_w1, g_w1);
    cudaGetSymbolAddress((void**)&p_wqkv, g_wqkv);
    cudaGetSymbolAddress((void**)&p_w3, g_w3);

    dim3 blk256(256);
    // x tf32 pre-round
    {
        int n4 = NB * CIN * HW / 4;
        k_round<<<(n4 + 255) / 256, blk256>>>((const float4*)x, (float4*)p_x, n4);
    }
    // weight repack (fragment order + tf32 round)
    k_repack<<<(MID * CIN + 255) / 256, blk256>>>(conv1_w, p_w1, MID, CIN);
    k_repack<<<(1024 * MID + 255) / 256, blk256>>>(qk_w, p_wqkv, 1024, MID);
    k_repack<<<(512 * MID + 255) / 256, blk256>>>(v_w, p_wqkv + (size_t)8 * 16 * ASZ,
                                                  512, MID);
    k_repack<<<(CIN * MID + 255) / 256, blk256>>>(conv3_w, p_w3, CIN, MID);

    k_gemm1<<<dim3(8, 4, NB), blk256, GEMM_SMEM>>>(gamma1, beta1, mean1, var1);
    k_gemm2<<<dim3(8, 12, NB), blk256, GEMM_SMEM>>>(pos_h, pos_w);
    k_flash<<<dim3(8, 1, NB * NHEAD), dim3(512), FLASH_SMEM>>>();
    k_gemm3<<<dim3(8, 16, NB), blk256, GEMM_SMEM>>>(gamma3, beta3, mean3, var3, x, out);
}

// round 8
// speedup vs baseline: 3.2301x; 1.0225x over previous
#include <cuda_runtime.h>
#include <cuda_bf16.h>
#include <cstdint>
#include <cstddef>

// Problem constants
#define NB   16
#define CIN  2048
#define MID  512
#define HW   1024
#define DQK  128
#define NHEAD 4
#define ATT_SCALE 0.08838834764831845f
#define BN_EPS 1e-5f

// GEMM tile: block 128(pos) x 128(ch), K-chunk 32, 8 warps of 32(pos)x64(ch)
#define LDA_P 136                       // A smem row pad (k rows of 128 pos)
#define A_ST  (32 * LDA_P)              // 4352 floats per A stage
#define B_ST  4096                      // packed B floats per stage (16KB)
#define GEMM_SMEM ((3 * A_ST + 3 * B_ST) * 4)   // 101376 B

// Flash tile config: x-tile 128, 512 threads (16 warps of 32x32)
#define LDB  136
#define BSZ (32 * LDB)
#define FLDQ 132
#define F_S  (128 * FLDQ)
#define F_B  (2 * F_S)
#define F_M  (F_B + 3 * BSZ)
#define F_L  (F_M + 128)
#define F_SC (F_L + 128)
#define FLASH_SMEM ((F_SC + 128) * 4)  // 188928 B

// Scratch (device globals — allocation-free kernel_launch)
__device__ float g_x   [(size_t)NB * CIN * HW];   // tf32-rounded x [n][ch][pos]
__device__ float g_out1[(size_t)NB * MID * HW];   // [n][ch][pos], tf32
__device__ float g_qk  [(size_t)NB * 1024 * HW];  // q'[d][x] then k'[d][y], tf32
__device__ float g_vT  [(size_t)NB * HW * MID];   // v [n][y][ch], tf32
__device__ float g_attn[(size_t)NB * MID * HW];   // [n][ch][pos], tf32
__device__ float g_w1  [(size_t)MID * CIN];       // B-fragment-packed
__device__ float g_wqkv[(size_t)1536 * MID];      // B-fragment-packed
__device__ float g_w3  [(size_t)CIN * MID];       // B-fragment-packed

// ---------------------------------------------------------------------------
__device__ __forceinline__ float f2tf(float f) {
    uint32_t u;
    asm("cvt.rna.tf32.f32 %0, %1;" : "=r"(u) : "f"(f));
    return __uint_as_float(u);
}

__device__ __forceinline__ void cp16(float* dst, const float* src) {
    uint32_t d = (uint32_t)__cvta_generic_to_shared(dst);
    asm volatile("cp.async.cg.shared.global [%0], [%1], 16;\n" :: "r"(d), "l"(src));
}
#define CP_COMMIT asm volatile("cp.async.commit_group;\n" ::: "memory")
#define CP_WAIT0  asm volatile("cp.async.wait_group 0;\n" ::: "memory")
#define CP_WAIT1  asm volatile("cp.async.wait_group 1;\n" ::: "memory")

// ---------------------------------------------------------------------------
// elementwise tf32 round (x)
// ---------------------------------------------------------------------------
__global__ __launch_bounds__(256) void k_round(const float4* __restrict__ src,
                                               float4* __restrict__ dst, int n4) {
    int i = blockIdx.x * blockDim.x + threadIdx.x;
    if (i < n4) {
        float4 v = src[i];
        dst[i] = make_float4(f2tf(v.x), f2tf(v.y), f2tf(v.z), f2tf(v.w));
    }
}

// ---------------------------------------------------------------------------
// Weight repack into B-fragment order.
// W[Mout][K] row-major -> packed float index e:
//   e = tile*(K*128) + c*4096 + h*2048 + (ks*4+np)*128 + lane*4 + comp
//   nt = 2*np + (comp>>1); b_idx = comp&1
//   n  = tile*128 + h*64 + nt*8 + (lane>>2)
//   k  = c*32 + ks*8 + (lane&3) + b_idx*4
// ---------------------------------------------------------------------------
__global__ __launch_bounds__(256) void k_repack(const float* __restrict__ src,
                                                float* __restrict__ dst,
                                                int Mout, int K) {
    int e = blockIdx.x * 256 + threadIdx.x;
    if (e >= Mout * K) return;
    int nchunks = K >> 5;
    int comp = e & 3;
    int lane = (e >> 2) & 31;
    int t = e >> 7;
    int np = t & 3, ks = (t >> 2) & 3, h = (t >> 4) & 1;
    int rest = t >> 5;
    int c = rest % nchunks, tile = rest / nchunks;
    int nt = 2 * np + (comp >> 1);
    int n = tile * 128 + h * 64 + nt * 8 + (lane >> 2);
    int k = c * 32 + ks * 8 + (lane & 3) + (comp & 1) * 4;
    dst[e] = f2tf(src[(size_t)n * K + k]);
}

// ---------------------------------------------------------------------------
// Swapped MMA: A = activations [k][pos] (stride LDA_P), B = packed weights.
// warp tile 32(pos) x 64(ch): acc[2][8][4]; rows=pos, cols=ch.
// ---------------------------------------------------------------------------
__device__ __forceinline__ void warp_mma_s(const float* sA, const float* sBh,
                                           float acc[2][8][4],
                                           int wm, int lane) {
    int grp = lane >> 2, tg = lane & 3;
#pragma unroll
    for (int ks = 0; ks < 4; ks++) {
        float a[2][4];
#pragma unroll
        for (int mt = 0; mt < 2; mt++) {
            const float* ap = sA + (ks * 8 + tg) * LDA_P + wm * 32 + mt * 16 + grp;
            a[mt][0] = ap[0];
            a[mt][1] = ap[8];
            a[mt][2] = ap[4 * LDA_P];
            a[mt][3] = ap[4 * LDA_P + 8];
        }
#pragma unroll
        for (int np = 0; np < 4; np++) {
            float4 bv = *(const float4*)(sBh + (ks * 4 + np) * 128 + lane * 4);
#pragma unroll
            for (int mt = 0; mt < 2; mt++) {
                asm volatile(
                    "mma.sync.aligned.m16n8k8.row.col.f32.tf32.tf32.f32 "
                    "{%0,%1,%2,%3}, {%4,%5,%6,%7}, {%8,%9}, {%0,%1,%2,%3};\n"
                    : "+f"(acc[mt][2 * np][0]), "+f"(acc[mt][2 * np][1]),
                      "+f"(acc[mt][2 * np][2]), "+f"(acc[mt][2 * np][3])
                    : "r"(__float_as_uint(a[mt][0])), "r"(__float_as_uint(a[mt][1])),
                      "r"(__float_as_uint(a[mt][2])), "r"(__float_as_uint(a[mt][3])),
                      "r"(__float_as_uint(bv.x)), "r"(__float_as_uint(bv.y)));
            }
#pragma unroll
            for (int mt = 0; mt < 2; mt++) {
                asm volatile(
                    "mma.sync.aligned.m16n8k8.row.col.f32.tf32.tf32.f32 "
                    "{%0,%1,%2,%3}, {%4,%5,%6,%7}, {%8,%9}, {%0,%1,%2,%3};\n"
                    : "+f"(acc[mt][2 * np + 1][0]), "+f"(acc[mt][2 * np + 1][1]),
                      "+f"(acc[mt][2 * np + 1][2]), "+f"(acc[mt][2 * np + 1][3])
                    : "r"(__float_as_uint(a[mt][0])), "r"(__float_as_uint(a[mt][1])),
                      "r"(__float_as_uint(a[mt][2])), "r"(__float_as_uint(a[mt][3])),
                      "r"(__float_as_uint(bv.z)), "r"(__float_as_uint(bv.w)));
            }
        }
    }
}

// flash variant (unchanged): A row-major stride FLDQ, warp tile 32x32
__device__ __forceinline__ void warp_mma_f(const float* A, const float* sB,
                                           float acc[2][4][4],
                                           int wm, int wn, int lane) {
    int grp = lane >> 2, tg = lane & 3;
#pragma unroll
    for (int ks = 0; ks < 4; ks++) {
        int kk = ks * 8;
        uint32_t a[2][4];
#pragma unroll
        for (int mt = 0; mt < 2; mt++) {
            const float* base = A + (wm + mt * 16 + grp) * FLDQ + kk + tg;
            a[mt][0] = __float_as_uint(base[0]);
            a[mt][1] = __float_as_uint(base[8 * FLDQ]);
            a[mt][2] = __float_as_uint(base[4]);
            a[mt][3] = __float_as_uint(base[8 * FLDQ + 4]);
        }
#pragma unroll
        for (int nt = 0; nt < 4; nt++) {
            const float* bb = sB + (kk + tg) * LDB + wn + nt * 8 + grp;
            uint32_t b0 = __float_as_uint(bb[0]);
            uint32_t b1 = __float_as_uint(bb[4 * LDB]);
#pragma unroll
            for (int mt = 0; mt < 2; mt++) {
                asm volatile(
                    "mma.sync.aligned.m16n8k8.row.col.f32.tf32.tf32.f32 "
                    "{%0,%1,%2,%3}, {%4,%5,%6,%7}, {%8,%9}, {%0,%1,%2,%3};\n"
                    : "+f"(acc[mt][nt][0]), "+f"(acc[mt][nt][1]),
                      "+f"(acc[mt][nt][2]), "+f"(acc[mt][nt][3])
                    : "r"(a[mt][0]), "r"(a[mt][1]), "r"(a[mt][2]), "r"(a[mt][3]),
                      "r"(b0), "r"(b1));
            }
        }
    }
}

// ---------------------------------------------------------------------------
// GEMM mainloop: 3-stage cp.async pipeline, swapped operands.
// Aact: activations [ch][pos] (row stride HW), tile rows = K chunk.
// Bw:   packed weights for this 128-ch tile (4096 floats per chunk).
// ---------------------------------------------------------------------------
__device__ __forceinline__ void gemm_mainloop3(
    float* smp, const float* __restrict__ Aact, const float* __restrict__ Bw,
    int nchunks, float acc[2][8][4], int wm, int wh, int lane, int tid) {
    float* sA = smp;
    float* sB = smp + 3 * A_ST;
#pragma unroll
    for (int s = 0; s < 2; s++) {
        float* dA = sA + s * A_ST;
        const float* srcA = Aact + (size_t)(s * 32) * HW;
#pragma unroll
        for (int i = 0; i < 4; i++) {
            int g = tid + i * 256, k = g >> 5, pq = (g & 31) * 4;
            cp16(dA + k * LDA_P + pq, srcA + (size_t)k * HW + pq);
        }
        float* dB = sB + s * B_ST;
        const float* srcB = Bw + (size_t)s * B_ST;
#pragma unroll
        for (int i = 0; i < 4; i++)
            cp16(dB + tid * 4 + i * 1024, srcB + tid * 4 + i * 1024);
        CP_COMMIT;
    }
    for (int c = 0; c < nchunks; c++) {
        if (c == nchunks - 1) { CP_WAIT0; } else { CP_WAIT1; }
        __syncthreads();
        if (c + 2 < nchunks) {
            int s = (c + 2) % 3;
            float* dA = sA + s * A_ST;
            const float* srcA = Aact + (size_t)((c + 2) * 32) * HW;
#pragma unroll
            for (int i = 0; i < 4; i++) {
                int g = tid + i * 256, k = g >> 5, pq = (g & 31) * 4;
                cp16(dA + k * LDA_P + pq, srcA + (size_t)k * HW + pq);
            }
            float* dB = sB + s * B_ST;
            const float* srcB = Bw + (size_t)(c + 2) * B_ST;
#pragma unroll
            for (int i = 0; i < 4; i++)
                cp16(dB + tid * 4 + i * 1024, srcB + tid * 4 + i * 1024);
            CP_COMMIT;
        }
        warp_mma_s(sA + (c % 3) * A_ST, sB + (c % 3) * B_ST + wh * 2048,
                   acc, wm, lane);
    }
}

// ---------------------------------------------------------------------------
// GEMM1: out1[ch][pos] = tf32(relu(BN(x^T @ w1^T)))   K=2048
// grid: (pos-tiles 8, ch-tiles 4, NB)
// ---------------------------------------------------------------------------
__global__ __launch_bounds__(256, 2) void k_gemm1(
    const float* __restrict__ gamma, const float* __restrict__ beta,
    const float* __restrict__ mean, const float* __restrict__ var) {
    extern __shared__ float smp[];
    int n = blockIdx.z, p0 = blockIdx.x * 128, c0 = blockIdx.y * 128;
    int tid = threadIdx.x, lane = tid & 31, warp = tid >> 5;
    int wm = warp & 3, wh = warp >> 2;
    int grp = lane >> 2, tg = lane & 3;
    float acc[2][8][4] = {};
    gemm_mainloop3(smp, g_x + (size_t)n * CIN * HW + p0,
                   g_w1 + (size_t)blockIdx.y * (CIN * 128), CIN / 32,
                   acc, wm, wh, lane, tid);
    float* outb = g_out1 + (size_t)n * MID * HW;
#pragma unroll
    for (int nt = 0; nt < 8; nt++) {
        int ch = c0 + wh * 64 + nt * 8 + 2 * tg;
        float i0 = gamma[ch] * rsqrtf(var[ch] + BN_EPS);
        float b0 = beta[ch] - mean[ch] * i0;
        float i1 = gamma[ch + 1] * rsqrtf(var[ch + 1] + BN_EPS);
        float b1 = beta[ch + 1] - mean[ch + 1] * i1;
#pragma unroll
        for (int mt = 0; mt < 2; mt++) {
            int p = p0 + wm * 32 + mt * 16 + grp;
            float* a4 = acc[mt][nt];
            outb[(size_t)ch * HW + p]           = f2tf(fmaxf(a4[0] * i0 + b0, 0.f));
            outb[(size_t)(ch + 1) * HW + p]     = f2tf(fmaxf(a4[1] * i1 + b1, 0.f));
            outb[(size_t)ch * HW + p + 8]       = f2tf(fmaxf(a4[2] * i0 + b0, 0.f));
            outb[(size_t)(ch + 1) * HW + p + 8] = f2tf(fmaxf(a4[3] * i1 + b1, 0.f));
        }
    }
}

// ---------------------------------------------------------------------------
// GEMM2: q'/k'/v projections   N=1536 ch, K=512.  grid (8, 12, NB)
// ch-tiles 0-3: q' ; 4-7: k'+emb ; 8-11: v -> g_vT
// ---------------------------------------------------------------------------
__global__ __launch_bounds__(256, 2) void k_gemm2(
    const float* __restrict__ pos_h, const float* __restrict__ pos_w) {
    extern __shared__ float smp[];
    int n = blockIdx.z, p0 = blockIdx.x * 128, c0 = blockIdx.y * 128;
    int tid = threadIdx.x, lane = tid & 31, warp = tid >> 5;
    int wm = warp & 3, wh = warp >> 2;
    int grp = lane >> 2, tg = lane & 3;
    float acc[2][8][4] = {};
    gemm_mainloop3(smp, g_out1 + (size_t)n * MID * HW + p0,
                   g_wqkv + (size_t)blockIdx.y * (MID * 128), MID / 32,
                   acc, wm, wh, lane, tid);
#pragma unroll
    for (int nt = 0; nt < 8; nt++) {
        int ch = c0 + wh * 64 + nt * 8 + 2 * tg;
#pragma unroll
        for (int mt = 0; mt < 2; mt++) {
            int p = p0 + wm * 32 + mt * 16 + grp;
            float* a4 = acc[mt][nt];
            if (c0 < 512) {                          // q' = tf32(q * scale)
                float* q = g_qk + ((size_t)n * 1024 + ch) * HW;
                q[p]          = f2tf(a4[0] * ATT_SCALE);
                q[HW + p]     = f2tf(a4[1] * ATT_SCALE);
                q[p + 8]      = f2tf(a4[2] * ATT_SCALE);
                q[HW + p + 8] = f2tf(a4[3] * ATT_SCALE);
            } else if (c0 < 1024) {                  // k' = tf32(k + emb[y,d])
                int d0 = ch & 127, d1 = (ch + 1) & 127;
                float* q = g_qk + ((size_t)n * 1024 + ch) * HW;
                int pa = p, pb = p + 8;
                float e00 = pos_h[(pa >> 5) * DQK + d0] + pos_w[(pa & 31) * DQK + d0];
                float e01 = pos_h[(pa >> 5) * DQK + d1] + pos_w[(pa & 31) * DQK + d1];
                float e10 = pos_h[(pb >> 5) * DQK + d0] + pos_w[(pb & 31) * DQK + d0];
                float e11 = pos_h[(pb >> 5) * DQK + d1] + pos_w[(pb & 31) * DQK + d1];
                q[pa]          = f2tf(a4[0] + e00);
                q[HW + pa]     = f2tf(a4[1] + e01);
                q[pb]          = f2tf(a4[2] + e10);
                q[HW + pb]     = f2tf(a4[3] + e11);
            } else {                                 // v -> g_vT[y][ch]
                int d = ch - 1024;
                float* v0 = g_vT + ((size_t)n * HW + p) * MID + d;
                float* v1 = g_vT + ((size_t)n * HW + p + 8) * MID + d;
                *(float2*)v0 = make_float2(f2tf(a4[0]), f2tf(a4[1]));
                *(float2*)v1 = make_float2(f2tf(a4[2]), f2tf(a4[3]));
            }
        }
    }
}

// ---------------------------------------------------------------------------
// Flash attention: x-tile 128, 512 threads, 3-buffer cp.async K/V ring.
// ---------------------------------------------------------------------------
__global__ __launch_bounds__(512) void k_flash() {
    extern __shared__ float sm[];
    float* Qs    = sm;
    float* Ss    = sm + F_S;
    float* sBr   = sm + F_B;
    float* sm_m  = sm + F_M;
    float* sm_l  = sm + F_L;
    float* sm_sc = sm + F_SC;

    int z = blockIdx.z, n = z >> 2, head = z & 3;
    int x0 = blockIdx.x * 128;
    int tid = threadIdx.x, lane = tid & 31, warp = tid >> 5;
    int wm = (warp & 3) * 32, wn = (warp >> 2) * 32;
    int grp = lane >> 2, tg = lane & 3;

    const float* qp = g_qk + ((size_t)n * 1024 + head * DQK) * HW;
    const float* kp = qp + (size_t)512 * HW;
    const float* vp = g_vT + (size_t)n * HW * MID + head * DQK;

    auto load_chunk = [&](int t) {
        float* buf = sBr + (t % 3) * BSZ;
        int j = t >> 3, ph = t & 7;
        const float* src;
        int ld;
        if (ph < 4) { src = kp + ((size_t)ph * 32) * HW + j * 128; ld = HW; }
        else        { src = vp + ((size_t)(j * 128 + (ph - 4) * 32)) * MID; ld = MID; }
#pragma unroll
        for (int i = 0; i < 2; i++) {
            int g = tid + i * 512, k = g >> 5, nq = (g & 31) * 4;
            cp16(buf + k * LDB + nq, src + (size_t)k * ld + nq);
        }
    };

    load_chunk(0); CP_COMMIT;
    load_chunk(1); CP_COMMIT;

#pragma unroll
    for (int i = 0; i < 8; i++) {
        int g = tid + i * 512;
        int d = g >> 5, xq = (g & 31) * 4;
        float4 v = *(const float4*)(qp + (size_t)d * HW + x0 + xq);
        Qs[(xq + 0) * FLDQ + d] = v.x;
        Qs[(xq + 1) * FLDQ + d] = v.y;
        Qs[(xq + 2) * FLDQ + d] = v.z;
        Qs[(xq + 3) * FLDQ + d] = v.w;
    }
    if (tid < 128) { sm_m[tid] = -1e30f; sm_l[tid] = 0.f; }
    float acc_o[2][4][4] = {};
    float acc_s[2][4][4] = {};
    __syncthreads();

    for (int j = 0; j < 8; j++) {
        for (int c = 0; c < 4; c++) {
            int t = j * 8 + c;
            if (t == 63) { CP_WAIT0; } else { CP_WAIT1; }
            __syncthreads();
            if (t + 2 < 64) { load_chunk(t + 2); CP_COMMIT; }
            warp_mma_f(Qs + c * 32, sBr + (t % 3) * BSZ, acc_s, wm, wn, lane);
        }
        __syncthreads();
#pragma unroll
        for (int mt = 0; mt < 2; mt++) {
            int r0 = wm + mt * 16 + grp, r1 = r0 + 8;
#pragma unroll
            for (int nt = 0; nt < 4; nt++) {
                int c = wn + nt * 8 + 2 * tg;
                Ss[r0 * FLDQ + c]     = acc_s[mt][nt][0];
                Ss[r0 * FLDQ + c + 1] = acc_s[mt][nt][1];
                Ss[r1 * FLDQ + c]     = acc_s[mt][nt][2];
                Ss[r1 * FLDQ + c + 1] = acc_s[mt][nt][3];
                acc_s[mt][nt][0] = acc_s[mt][nt][1] = 0.f;
                acc_s[mt][nt][2] = acc_s[mt][nt][3] = 0.f;
            }
        }
        __syncthreads();
        {
            int r = tid >> 2, q = tid & 3;
            float* row = Ss + r * FLDQ;
            float mloc = -1e30f;
#pragma unroll
            for (int i = 0; i < 32; i++) mloc = fmaxf(mloc, row[q + 4 * i]);
            mloc = fmaxf(mloc, __shfl_xor_sync(0xffffffff, mloc, 1));
            mloc = fmaxf(mloc, __shfl_xor_sync(0xffffffff, mloc, 2));
            float m_old = sm_m[r];
            float m_new = fmaxf(m_old, mloc);
            float s = 0.f;
#pragma unroll
            for (int i = 0; i < 32; i++) {
                float p = __expf(row[q + 4 * i] - m_new);
                row[q + 4 * i] = f2tf(p);
                s += p;
            }
            s += __shfl_xor_sync(0xffffffff, s, 1);
            s += __shfl_xor_sync(0xffffffff, s, 2);
            if (q == 0) {
                sm_sc[r] = __expf(m_old - m_new);
                sm_m[r]  = m_new;
                sm_l[r]  = sm_l[r] * sm_sc[r] + s;
            }
        }
        __syncthreads();
#pragma unroll
        for (int mt = 0; mt < 2; mt++) {
            int r0 = wm + mt * 16 + grp;
            float s0 = sm_sc[r0], s1 = sm_sc[r0 + 8];
#pragma unroll
            for (int nt = 0; nt < 4; nt++) {
                acc_o[mt][nt][0] *= s0; acc_o[mt][nt][1] *= s0;
                acc_o[mt][nt][2] *= s1; acc_o[mt][nt][3] *= s1;
            }
        }
        for (int c = 0; c < 4; c++) {
            int t = j * 8 + 4 + c;
            if (t == 63) { CP_WAIT0; } else { CP_WAIT1; }
            __syncthreads();
            if (t + 2 < 64) { load_chunk(t + 2); CP_COMMIT; }
            warp_mma_f(Ss + c * 32, sBr + (t % 3) * BSZ, acc_o, wm, wn, lane);
        }
    }

    __syncthreads();
#pragma unroll
    for (int mt = 0; mt < 2; mt++) {
        int r0 = wm + mt * 16 + grp, r1 = r0 + 8;
        float l0 = 1.f / sm_l[r0], l1 = 1.f / sm_l[r1];
#pragma unroll
        for (int nt = 0; nt < 4; nt++) {
            int c = wn + nt * 8 + 2 * tg;
            Ss[r0 * FLDQ + c]     = fmaxf(acc_o[mt][nt][0] * l0, 0.f);
            Ss[r0 * FLDQ + c + 1] = fmaxf(acc_o[mt][nt][1] * l0, 0.f);
            Ss[r1 * FLDQ + c]     = fmaxf(acc_o[mt][nt][2] * l1, 0.f);
            Ss[r1 * FLDQ + c + 1] = fmaxf(acc_o[mt][nt][3] * l1, 0.f);
        }
    }
    __syncthreads();
    float* op = g_attn + ((size_t)n * MID + head * DQK) * HW;
#pragma unroll
    for (int i = 0; i < 32; i++) {
        int g = tid + i * 512;
        int d = g >> 7, xo = g & 127;
        op[(size_t)d * HW + x0 + xo] = f2tf(Ss[xo * FLDQ + d]);
    }
}

// ---------------------------------------------------------------------------
// GEMM3: out[ch][pos] = relu(BN(attn^T @ w3^T) + x)   N=2048 ch, K=512
// grid (8, 16, NB)
// ---------------------------------------------------------------------------
__global__ __launch_bounds__(256, 2) void k_gemm3(
    const float* __restrict__ gamma, const float* __restrict__ beta,
    const float* __restrict__ mean, const float* __restrict__ var,
    const float* __restrict__ x, float* __restrict__ out) {
    extern __shared__ float smp[];
    int n = blockIdx.z, p0 = blockIdx.x * 128, c0 = blockIdx.y * 128;
    int tid = threadIdx.x, lane = tid & 31, warp = tid >> 5;
    int wm = warp & 3, wh = warp >> 2;
    int grp = lane >> 2, tg = lane & 3;
    float acc[2][8][4] = {};
    gemm_mainloop3(smp, g_attn + (size_t)n * MID * HW + p0,
                   g_w3 + (size_t)blockIdx.y * (MID * 128), MID / 32,
                   acc, wm, wh, lane, tid);
#pragma unroll
    for (int nt = 0; nt < 8; nt++) {
        int ch = c0 + wh * 64 + nt * 8 + 2 * tg;
        float i0 = gamma[ch] * rsqrtf(var[ch] + BN_EPS);
        float b0 = beta[ch] - mean[ch] * i0;
        float i1 = gamma[ch + 1] * rsqrtf(var[ch + 1] + BN_EPS);
        float b1 = beta[ch + 1] - mean[ch + 1] * i1;
#pragma unroll
        for (int mt = 0; mt < 2; mt++) {
            int p = p0 + wm * 32 + mt * 16 + grp;
            float* a4 = acc[mt][nt];
            size_t e0 = (size_t)n * CIN * HW + (size_t)ch * HW + p;
            size_t e1 = e0 + HW;            // ch+1, same pos
            out[e0]     = fmaxf(a4[0] * i0 + b0 + x[e0], 0.f);
            out[e1]     = fmaxf(a4[1] * i1 + b1 + x[e1], 0.f);
            out[e0 + 8] = fmaxf(a4[2] * i0 + b0 + x[e0 + 8], 0.f);
            out[e1 + 8] = fmaxf(a4[3] * i1 + b1 + x[e1 + 8], 0.f);
        }
    }
}

// ---------------------------------------------------------------------------
extern "C" void kernel_launch(void* const* d_in, const int* in_sizes, int n_in,
                              void* d_out, int out_size) {
    const float* x       = (const float*)d_in[0];
    const float* conv1_w = (const float*)d_in[1];
    const float* gamma1  = (const float*)d_in[2];
    const float* beta1   = (const float*)d_in[3];
    const float* mean1   = (const float*)d_in[4];
    const float* var1    = (const float*)d_in[5];
    const float* qk_w    = (const float*)d_in[6];
    const float* v_w     = (const float*)d_in[7];
    const float* pos_h   = (const float*)d_in[8];
    const float* pos_w   = (const float*)d_in[9];
    const float* conv3_w = (const float*)d_in[10];
    const float* gamma3  = (const float*)d_in[11];
    const float* beta3   = (const float*)d_in[12];
    const float* mean3   = (const float*)d_in[13];
    const float* var3    = (const float*)d_in[14];
    float* out = (float*)d_out;

    cudaFuncSetAttribute(k_flash, cudaFuncAttributeMaxDynamicSharedMemorySize,
                         FLASH_SMEM);
    cudaFuncSetAttribute(k_gemm1, cudaFuncAttributeMaxDynamicSharedMemorySize,
                         GEMM_SMEM);
    cudaFuncSetAttribute(k_gemm2, cudaFuncAttributeMaxDynamicSharedMemorySize,
                         GEMM_SMEM);
    cudaFuncSetAttribute(k_gemm3, cudaFuncAttributeMaxDynamicSharedMemorySize,
                         GEMM_SMEM);

    float *p_x, *p_w1, *p_wqkv, *p_w3;
    cudaGetSymbolAddress((void**)&p_x, g_x);
    cudaGetSymbolAddress((void**)&p_w1, g_w1);
    cudaGetSymbolAddress((void**)&p_wqkv, g_wqkv);
    cudaGetSymbolAddress((void**)&p_w3, g_w3);

    dim3 blk256(256);
    {
        int n4 = NB * CIN * HW / 4;
        k_round<<<(n4 + 255) / 256, blk256>>>((const float4*)x, (float4*)p_x, n4);
    }
    // weight repack into B-fragment order (+ tf32 round)
    k_repack<<<(MID * CIN + 255) / 256, blk256>>>(conv1_w, p_w1, MID, CIN);
    k_repack<<<(1024 * MID + 255) / 256, blk256>>>(qk_w, p_wqkv, 1024, MID);
    k_repack<<<(512 * MID + 255) / 256, blk256>>>(v_w, p_wqkv + (size_t)1024 * MID,
                                                  512, MID);
    k_repack<<<(CIN * MID + 255) / 256, blk256>>>(conv3_w, p_w3, CIN, MID);

    k_gemm1<<<dim3(8, 4, NB), blk256, GEMM_SMEM>>>(gamma1, beta1, mean1, var1);
    k_gemm2<<<dim3(8, 12, NB), blk256, GEMM_SMEM>>>(pos_h, pos_w);
    k_flash<<<dim3(8, 1, NB * NHEAD), dim3(512), FLASH_SMEM>>>();
    k_gemm3<<<dim3(8, 16, NB), blk256, GEMM_SMEM>>>(gamma3, beta3, mean3, var3, x, out);
}